// round 1
// baseline (speedup 1.0000x reference)
#include <cuda_runtime.h>
#include <cuda_bf16.h>
#include <math.h>

#define BDIM 1024
#define DDIM 512
#define CDIM 100000
#define SCALE 64.0f
#define MARGIN 0.35f
#define NCHUNK ((CDIM + 63) / 64)   // 1563

// ---------------- scratch (static device memory; no allocations) -------------
__device__ int   g_is64;
__device__ float g_rnx[BDIM];
__device__ float g_rwn[CDIM];
__device__ float g_partial[BDIM * NCHUNK];   // [row][chunk]
__device__ float g_tgt[BDIM];
__device__ float g_rowloss[BDIM];

// ---------------- label dtype handling ---------------------------------------
__device__ __forceinline__ int get_label(const void* p, int i) {
    if (g_is64) return (int)((const long long*)p)[i];
    return ((const int*)p)[i];
}

// Detect int64 vs int32 labels. Reads only the first BDIM/2 int64 slots, which
// stays inside the buffer for either dtype. If the data is really int32, the
// combined 64-bit reads will contain huge/out-of-range values with prob ~1.
__global__ void detect_kernel(const void* __restrict__ lab) {
    __shared__ int ok;
    if (threadIdx.x == 0) ok = 1;
    __syncthreads();
    const long long* q = (const long long*)lab;
    for (int i = threadIdx.x; i < BDIM / 2; i += blockDim.x) {
        long long v = q[i];
        if (v < 0 || v >= (long long)CDIM) ok = 0;
    }
    __syncthreads();
    if (threadIdx.x == 0) g_is64 = ok;
}

// ---------------- reciprocal row norms ---------------------------------------
// which == 0 -> g_rnx (input rows), which == 1 -> g_rwn (weight rows)
__global__ void rownorm_kernel(const float* __restrict__ p, int nrows, int which) {
    int w    = (blockIdx.x * blockDim.x + threadIdx.x) >> 5;
    int lane = threadIdx.x & 31;
    if (w >= nrows) return;
    const float4* pr = (const float4*)(p + (long long)w * DDIM);
    float s = 0.f;
    #pragma unroll 4
    for (int k = lane; k < DDIM / 4; k += 32) {
        float4 a = pr[k];
        s += a.x * a.x + a.y * a.y + a.z * a.z + a.w * a.w;
    }
    #pragma unroll
    for (int off = 16; off >= 1; off >>= 1)
        s += __shfl_xor_sync(0xffffffffu, s, off);
    if (lane == 0) {
        float r = 1.0f / fmaxf(sqrtf(s), 1e-12f);
        if (which) g_rwn[w] = r; else g_rnx[w] = r;
    }
}

// ---------------- fused GEMM + margin + exp + per-row partial sums -----------
// Block: 256 threads, tile 64 rows (batch) x 64 cols (classes), BK = 32.
// blockIdx.x = batch chunk (fast, 16), blockIdx.y = class chunk (1563).
__global__ __launch_bounds__(256) void cos_main(const float* __restrict__ input,
                                                const void*  __restrict__ label,
                                                const float* __restrict__ weight) {
    __shared__ float As[32][68];
    __shared__ float Ws[32][68];
    __shared__ int   lab_s[64];

    const int t  = threadIdx.x;
    const int tx = t & 15;
    const int ty = t >> 4;
    const int rowBase = blockIdx.x * 64;
    const int colBase = blockIdx.y * 64;

    if (t < 64) lab_s[t] = get_label(label, rowBase + t);

    float acc[4][4];
    #pragma unroll
    for (int i = 0; i < 4; ++i)
        #pragma unroll
        for (int j = 0; j < 4; ++j) acc[i][j] = 0.f;

    for (int k0 = 0; k0 < DDIM; k0 += 32) {
        __syncthreads();
        #pragma unroll
        for (int it = 0; it < 2; ++it) {
            int q  = t + it * 256;
            int r  = q >> 3;          // 0..63
            int kq = q & 7;           // 0..7 -> k = kq*4..kq*4+3
            // input tile (normalized on load)
            {
                int rg = rowBase + r;
                float4 v  = *(const float4*)(input + (long long)rg * DDIM + k0 + kq * 4);
                float  rn = g_rnx[rg];
                As[kq * 4 + 0][r] = v.x * rn;
                As[kq * 4 + 1][r] = v.y * rn;
                As[kq * 4 + 2][r] = v.z * rn;
                As[kq * 4 + 3][r] = v.w * rn;
            }
            // weight tile (normalized on load, OOB classes -> 0)
            {
                int cg = colBase + r;
                float4 v  = make_float4(0.f, 0.f, 0.f, 0.f);
                float  rn = 0.f;
                if (cg < CDIM) {
                    v  = *(const float4*)(weight + (long long)cg * DDIM + k0 + kq * 4);
                    rn = g_rwn[cg];
                }
                Ws[kq * 4 + 0][r] = v.x * rn;
                Ws[kq * 4 + 1][r] = v.y * rn;
                Ws[kq * 4 + 2][r] = v.z * rn;
                Ws[kq * 4 + 3][r] = v.w * rn;
            }
        }
        __syncthreads();
        #pragma unroll
        for (int k = 0; k < 32; ++k) {
            float4 a = *(const float4*)&As[k][ty * 4];
            float4 w = *(const float4*)&Ws[k][tx * 4];
            float av[4] = {a.x, a.y, a.z, a.w};
            float wv[4] = {w.x, w.y, w.z, w.w};
            #pragma unroll
            for (int i = 0; i < 4; ++i)
                #pragma unroll
                for (int j = 0; j < 4; ++j)
                    acc[i][j] = fmaf(av[i], wv[j], acc[i][j]);
        }
    }

    // Epilogue: logits -> exp -> per-row partial sum over this class chunk.
    #pragma unroll
    for (int i = 0; i < 4; ++i) {
        int   rl  = ty * 4 + i;
        int   lab = lab_s[rl];
        float s   = 0.f;
        #pragma unroll
        for (int j = 0; j < 4; ++j) {
            int cg = colBase + tx * 4 + j;
            if (cg < CDIM) {
                float logit = SCALE * acc[i][j];
                if (cg == lab) logit -= SCALE * MARGIN;
                s += __expf(logit);
            }
        }
        // reduce across the 16 tx lanes of this row (bit 4 = ty parity, untouched)
        #pragma unroll
        for (int off = 8; off >= 1; off >>= 1)
            s += __shfl_xor_sync(0xffffffffu, s, off);
        if (tx == 0)
            g_partial[(rowBase + rl) * NCHUNK + blockIdx.y] = s;
    }
}

// ---------------- target (margin-adjusted) logit per row ---------------------
__global__ void target_kernel(const float* __restrict__ input,
                              const void*  __restrict__ label,
                              const float* __restrict__ weight) {
    int w    = (blockIdx.x * blockDim.x + threadIdx.x) >> 5;
    int lane = threadIdx.x & 31;
    if (w >= BDIM) return;
    int lab = get_label(label, w);
    const float4* xr = (const float4*)(input  + (long long)w   * DDIM);
    const float4* wr = (const float4*)(weight + (long long)lab * DDIM);
    float s = 0.f;
    #pragma unroll 4
    for (int k = lane; k < DDIM / 4; k += 32) {
        float4 a = xr[k], b = wr[k];
        s += a.x * b.x + a.y * b.y + a.z * b.z + a.w * b.w;
    }
    #pragma unroll
    for (int off = 16; off >= 1; off >>= 1)
        s += __shfl_xor_sync(0xffffffffu, s, off);
    if (lane == 0)
        g_tgt[w] = SCALE * (s * g_rnx[w] * g_rwn[lab] - MARGIN);
}

// ---------------- per-row logsumexp + loss -----------------------------------
__global__ void fin1_kernel() {
    int r = blockIdx.x;
    float s = 0.f;
    for (int i = threadIdx.x; i < NCHUNK; i += blockDim.x)
        s += g_partial[r * NCHUNK + i];
    #pragma unroll
    for (int off = 16; off >= 1; off >>= 1)
        s += __shfl_xor_sync(0xffffffffu, s, off);
    __shared__ float sm[4];
    int lane = threadIdx.x & 31, wid = threadIdx.x >> 5;
    if (lane == 0) sm[wid] = s;
    __syncthreads();
    if (threadIdx.x == 0) {
        float tot = sm[0] + sm[1] + sm[2] + sm[3];
        g_rowloss[r] = logf(tot) - g_tgt[r];
    }
}

// ---------------- mean over rows ---------------------------------------------
__global__ void fin2_kernel(float* __restrict__ out) {
    __shared__ float sm[32];
    float s = g_rowloss[threadIdx.x];
    #pragma unroll
    for (int off = 16; off >= 1; off >>= 1)
        s += __shfl_xor_sync(0xffffffffu, s, off);
    int lane = threadIdx.x & 31, wid = threadIdx.x >> 5;
    if (lane == 0) sm[wid] = s;
    __syncthreads();
    if (wid == 0) {
        float v = sm[lane];
        #pragma unroll
        for (int off = 16; off >= 1; off >>= 1)
            v += __shfl_xor_sync(0xffffffffu, v, off);
        if (lane == 0) out[0] = v * (1.0f / (float)BDIM);
    }
}

// ---------------- launch -----------------------------------------------------
extern "C" void kernel_launch(void* const* d_in, const int* in_sizes, int n_in,
                              void* d_out, int out_size) {
    const float* input  = (const float*)d_in[0];
    const void*  label  = d_in[1];
    const float* weight = (const float*)d_in[2];
    float* out = (float*)d_out;

    detect_kernel<<<1, 256>>>(label);
    rownorm_kernel<<<(BDIM * 32 + 255) / 256, 256>>>(input, BDIM, 0);
    rownorm_kernel<<<((long long)CDIM * 32 + 255) / 256, 256>>>(weight, CDIM, 1);

    dim3 grid(BDIM / 64, NCHUNK);   // batch chunks fast -> weight-tile L2 reuse
    cos_main<<<grid, 256>>>(input, label, weight);

    target_kernel<<<(BDIM * 32 + 255) / 256, 256>>>(input, label, weight);
    fin1_kernel<<<BDIM, 128>>>();
    fin2_kernel<<<1, BDIM>>>(out);
}

// round 3
// speedup vs baseline: 5.1256x; 5.1256x over previous
#include <cuda_runtime.h>
#include <cuda_bf16.h>
#include <cstdint>
#include <math.h>

#define BDIM 1024
#define DDIM 512
#define CDIM 100000
#define SCALE 64.0f
#define MARGIN 0.35f
#define TM 128
#define TN 128
#define NT2 ((CDIM + TN - 1) / TN)   // 782 class tiles
#define NBT (BDIM / TM)              // 8 batch tiles
#define KS 72                        // smem row stride in bf16 (144B)

// ---------------- static scratch ---------------------------------------------
__device__ int   g_is64;
__device__ float g_rnx[BDIM];
__device__ float g_rwn[CDIM];
__device__ __nv_bfloat16 g_xb[BDIM * DDIM];
__device__ __nv_bfloat16 g_wb[(size_t)CDIM * DDIM];
__device__ float g_partial[BDIM * NT2];
__device__ float g_tgt[BDIM];
__device__ float g_rowloss[BDIM];

// ---------------- helpers -----------------------------------------------------
__device__ __forceinline__ uint32_t smem_u32(const void* p) {
    uint32_t a;
    asm("{ .reg .u64 t; cvta.to.shared.u64 t, %1; cvt.u32.u64 %0, t; }" : "=r"(a) : "l"(p));
    return a;
}
__device__ __forceinline__ void cpa16(uint32_t dst, const void* src, int pred) {
    int sz = pred ? 16 : 0;
    asm volatile("cp.async.cg.shared.global [%0], [%1], 16, %2;" :: "r"(dst), "l"(src), "r"(sz));
}
#define CP_COMMIT() asm volatile("cp.async.commit_group;" ::: "memory")
#define CP_WAIT1()  asm volatile("cp.async.wait_group 1;" ::: "memory")
#define CP_WAIT0()  asm volatile("cp.async.wait_group 0;" ::: "memory")

#define LDSM4(r0, r1, r2, r3, a) \
    asm volatile("ldmatrix.sync.aligned.m8n8.x4.shared.b16 {%0,%1,%2,%3}, [%4];" \
                 : "=r"(r0), "=r"(r1), "=r"(r2), "=r"(r3) : "r"(a))

#define MMA16816(d, a, b) \
    asm volatile("mma.sync.aligned.m16n8k16.row.col.f32.bf16.bf16.f32 " \
                 "{%0,%1,%2,%3}, {%4,%5,%6,%7}, {%8,%9}, {%0,%1,%2,%3};" \
                 : "+f"((d)[0]), "+f"((d)[1]), "+f"((d)[2]), "+f"((d)[3]) \
                 : "r"((a)[0]), "r"((a)[1]), "r"((a)[2]), "r"((a)[3]), "r"((b)[0]), "r"((b)[1]))

// ---------------- label dtype ------------------------------------------------
__device__ __forceinline__ int get_label(const void* p, int i) {
    if (g_is64) return (int)((const long long*)p)[i];
    return ((const int*)p)[i];
}
__global__ void detect_kernel(const void* __restrict__ lab) {
    __shared__ int ok;
    if (threadIdx.x == 0) ok = 1;
    __syncthreads();
    const long long* q = (const long long*)lab;
    for (int i = threadIdx.x; i < BDIM / 2; i += blockDim.x) {
        long long v = q[i];
        if (v < 0 || v >= (long long)CDIM) ok = 0;
    }
    __syncthreads();
    if (threadIdx.x == 0) g_is64 = ok;
}

// ---------------- normalize + cast to bf16 ------------------------------------
__global__ void norm_cast_kernel(const float* __restrict__ p, int nrows, int which) {
    int w    = (blockIdx.x * blockDim.x + threadIdx.x) >> 5;
    int lane = threadIdx.x & 31;
    if (w >= nrows) return;
    const float4* pr = (const float4*)(p + (long long)w * DDIM);
    float s = 0.f;
    #pragma unroll 4
    for (int k = lane; k < DDIM / 4; k += 32) {
        float4 a = pr[k];
        s += a.x * a.x + a.y * a.y + a.z * a.z + a.w * a.w;
    }
    #pragma unroll
    for (int off = 16; off >= 1; off >>= 1)
        s += __shfl_xor_sync(0xffffffffu, s, off);
    float r = 1.0f / fmaxf(sqrtf(s), 1e-12f);
    if (lane == 0) { if (which) g_rwn[w] = r; else g_rnx[w] = r; }
    __nv_bfloat162* d2 = (__nv_bfloat162*)((which ? g_wb : g_xb) + (long long)w * DDIM);
    const float2* p2 = (const float2*)(p + (long long)w * DDIM);
    #pragma unroll
    for (int j = 0; j < 8; ++j) {
        int e2 = lane * 8 + j;
        float2 v = p2[e2];
        d2[e2] = __floats2bfloat162_rn(v.x * r, v.y * r);
    }
}

// ---------------- fast exp (FFMA pipe) ----------------------------------------
__device__ __forceinline__ float fexp(float x) {
    float tt = x * 1.44269504f;
    float fi = rintf(tt);
    float f  = tt - fi;
    float p  = 1.535336188319500e-4f;
    p = fmaf(p, f, 1.339887440266574e-3f);
    p = fmaf(p, f, 9.618437357674640e-3f);
    p = fmaf(p, f, 5.550332471162809e-2f);
    p = fmaf(p, f, 2.402264791363012e-1f);
    p = fmaf(p, f, 6.931472028550421e-1f);
    p = fmaf(p, f, 1.0f);
    int i = (int)fi;
    return p * __int_as_float((i + 127) << 23);
}

// smem layout (bytes): A0 @0 (18432), B0 @18432, A1 @36864, B1 @55296,
// labels @73728 (512), redbuf @74240 (2048) -> 76288 total
#define SA(b) ((b) * 36864u)
#define SB(b) (18432u + (b) * 36864u)
#define SM_LAB 73728
#define SM_RED 74240
#define SMEM_TOTAL 76288

// ---------------- main fused GEMM kernel --------------------------------------
__global__ __launch_bounds__(256, 2) void tile_kernel(const void* __restrict__ label) {
    extern __shared__ char smem[];
    const int t    = threadIdx.x;
    const int wid  = t >> 5;
    const int lane = t & 31;
    const int wm   = wid >> 2;       // 0..1 : m-slice of 64
    const int wn   = wid & 3;        // 0..3 : n-slice of 32
    const int rowBase = blockIdx.x * TM;
    const int colBase = blockIdx.y * TN;
    const uint32_t sb = smem_u32(smem);
    int*   labp = (int*)(smem + SM_LAB);
    float* red  = (float*)(smem + SM_RED);

    if (t < TM) labp[t] = get_label(label, rowBase + t);

    // ---- cp.async tile loaders (each thread: 4 sectors A + 4 sectors B) ----
    const int ldr = t >> 1;          // 0..127 row handled (2 threads per row)
    const int ldc = (t & 1) * 4;     // starting 16B-sector within row (0 or 4)
    const __nv_bfloat16* agp = g_xb + ((long long)(rowBase + ldr) << 9) + (ldc << 3);
    int cgB = colBase + ldr;
    int bpred = cgB < CDIM;
    const __nv_bfloat16* bgp = g_wb + ((long long)(bpred ? cgB : 0) << 9) + (ldc << 3);
    const uint32_t adst = sb + ldr * 144 + ldc * 16;
    const uint32_t bdst = sb + 18432 + ldr * 144 + ldc * 16;

    #define LOAD_CHUNK(kc, buf) do {                                        \
        const __nv_bfloat16* as = agp + ((kc) << 6);                        \
        const __nv_bfloat16* bs = bgp + ((kc) << 6);                        \
        uint32_t ad = adst + (buf) * 36864u;                                \
        uint32_t bd = bdst + (buf) * 36864u;                                \
        _Pragma("unroll")                                                   \
        for (int s = 0; s < 4; ++s) {                                       \
            cpa16(ad + s * 16, as + s * 8, 1);                              \
            cpa16(bd + s * 16, bs + s * 8, bpred);                          \
        }                                                                   \
        CP_COMMIT();                                                        \
    } while (0)

    LOAD_CHUNK(0, 0);
    LOAD_CHUNK(1, 1);

    // ---- per-lane ldmatrix base addresses ----
    // A: lanes 0-15 -> rows m0..15 (k+0), lanes 16-31 -> rows m0..15 (k+8)
    const int aRow = wm * 64 + (lane & 15);
    const int aKof = (lane >> 4) * 8;
    const uint32_t aAddrBase = sb + aRow * 144 + aKof * 2;
    // B (x4 covering two n8-tiles): g = lane>>3:
    //   g0: n+0..7 k+0 | g1: n+0..7 k+8 | g2: n+8..15 k+0 | g3: n+8..15 k+8
    const int g = lane >> 3;
    const int bRow = wn * 32 + ((g >> 1) << 3) + (lane & 7);
    const int bKof = (g & 1) * 8;
    const uint32_t bAddrBase = sb + 18432u + bRow * 144 + bKof * 2;

    float acc[4][4][4];
    #pragma unroll
    for (int mi = 0; mi < 4; ++mi)
        #pragma unroll
        for (int ni = 0; ni < 4; ++ni)
            #pragma unroll
            for (int c = 0; c < 4; ++c) acc[mi][ni][c] = 0.f;

    #pragma unroll 1
    for (int kc = 0; kc < 8; ++kc) {
        const int buf = kc & 1;
        CP_WAIT1();
        __syncthreads();
        const uint32_t aB = aAddrBase + buf * 36864u;
        const uint32_t bB = bAddrBase + buf * 36864u;
        #pragma unroll
        for (int ks = 0; ks < 4; ++ks) {
            uint32_t afr[4][4];
            uint32_t bfr[4][2];
            #pragma unroll
            for (int mi = 0; mi < 4; ++mi)
                LDSM4(afr[mi][0], afr[mi][1], afr[mi][2], afr[mi][3],
                      aB + mi * 16 * 144 + ks * 32);
            #pragma unroll
            for (int p = 0; p < 2; ++p)
                LDSM4(bfr[2 * p][0], bfr[2 * p][1], bfr[2 * p + 1][0], bfr[2 * p + 1][1],
                      bB + p * 16 * 144 + ks * 32);
            #pragma unroll
            for (int mi = 0; mi < 4; ++mi)
                #pragma unroll
                for (int ni = 0; ni < 4; ++ni)
                    MMA16816(acc[mi][ni], afr[mi], bfr[ni]);
        }
        __syncthreads();
        if (kc + 2 < 8) LOAD_CHUNK(kc + 2, buf);
        else CP_COMMIT();   // keep wait_group counts consistent
    }
    CP_WAIT0();

    // ---- epilogue: scale, margin, exp, per-row partials ----
    const int groupID = lane >> 2;
    const int tid4    = lane & 3;
    #pragma unroll
    for (int mi = 0; mi < 4; ++mi) {
        #pragma unroll
        for (int half = 0; half < 2; ++half) {
            const int rl  = wm * 64 + mi * 16 + groupID + half * 8;
            const int lab = labp[rl];
            float s = 0.f;
            #pragma unroll
            for (int ni = 0; ni < 4; ++ni) {
                const int c0 = colBase + wn * 32 + ni * 8 + tid4 * 2;
                #pragma unroll
                for (int cc = 0; cc < 2; ++cc) {
                    const int col = c0 + cc;
                    if (col < CDIM) {
                        float x = acc[mi][ni][half * 2 + cc] * SCALE;
                        if (col == lab) x -= SCALE * MARGIN;
                        s += fexp(x);
                    }
                }
            }
            s += __shfl_xor_sync(0xffffffffu, s, 1);
            s += __shfl_xor_sync(0xffffffffu, s, 2);
            if (tid4 == 0) red[rl * 4 + wn] = s;
        }
    }
    __syncthreads();
    if (t < TM) {
        float s = red[t * 4 + 0] + red[t * 4 + 1] + red[t * 4 + 2] + red[t * 4 + 3];
        g_partial[(rowBase + t) * NT2 + blockIdx.y] = s;
    }
}

// ---------------- exact fp32 target logit -------------------------------------
__global__ void target_kernel(const float* __restrict__ input,
                              const void*  __restrict__ label,
                              const float* __restrict__ weight) {
    int w    = (blockIdx.x * blockDim.x + threadIdx.x) >> 5;
    int lane = threadIdx.x & 31;
    if (w >= BDIM) return;
    int lab = get_label(label, w);
    const float4* xr = (const float4*)(input  + (long long)w   * DDIM);
    const float4* wr = (const float4*)(weight + (long long)lab * DDIM);
    float s = 0.f;
    #pragma unroll 4
    for (int k = lane; k < DDIM / 4; k += 32) {
        float4 a = xr[k], b = wr[k];
        s += a.x * b.x + a.y * b.y + a.z * b.z + a.w * b.w;
    }
    #pragma unroll
    for (int off = 16; off >= 1; off >>= 1)
        s += __shfl_xor_sync(0xffffffffu, s, off);
    if (lane == 0)
        g_tgt[w] = SCALE * (s * g_rnx[w] * g_rwn[lab] - MARGIN);
}

// ---------------- per-row logsumexp + loss ------------------------------------
__global__ void fin1_kernel() {
    int r = blockIdx.x;
    float s = 0.f;
    for (int i = threadIdx.x; i < NT2; i += blockDim.x)
        s += g_partial[r * NT2 + i];
    #pragma unroll
    for (int off = 16; off >= 1; off >>= 1)
        s += __shfl_xor_sync(0xffffffffu, s, off);
    __shared__ float sm[4];
    int lane = threadIdx.x & 31, wid = threadIdx.x >> 5;
    if (lane == 0) sm[wid] = s;
    __syncthreads();
    if (threadIdx.x == 0) {
        float tot = sm[0] + sm[1] + sm[2] + sm[3];
        g_rowloss[r] = logf(tot) - g_tgt[r];
    }
}
__global__ void fin2_kernel(float* __restrict__ out) {
    __shared__ float sm[32];
    float s = g_rowloss[threadIdx.x];
    #pragma unroll
    for (int off = 16; off >= 1; off >>= 1)
        s += __shfl_xor_sync(0xffffffffu, s, off);
    int lane = threadIdx.x & 31, wid = threadIdx.x >> 5;
    if (lane == 0) sm[wid] = s;
    __syncthreads();
    if (wid == 0) {
        float v = sm[lane];
        #pragma unroll
        for (int off = 16; off >= 1; off >>= 1)
            v += __shfl_xor_sync(0xffffffffu, v, off);
        if (lane == 0) out[0] = v * (1.0f / (float)BDIM);
    }
}

// ---------------- launch ------------------------------------------------------
extern "C" void kernel_launch(void* const* d_in, const int* in_sizes, int n_in,
                              void* d_out, int out_size) {
    const float* input  = (const float*)d_in[0];
    const void*  label  = d_in[1];
    const float* weight = (const float*)d_in[2];
    float* out = (float*)d_out;

    cudaFuncSetAttribute(tile_kernel, cudaFuncAttributeMaxDynamicSharedMemorySize, SMEM_TOTAL);

    detect_kernel<<<1, 256>>>(label);
    norm_cast_kernel<<<(BDIM * 32 + 255) / 256, 256>>>(input, BDIM, 0);
    norm_cast_kernel<<<(CDIM * 32 + 255) / 256, 256>>>(weight, CDIM, 1);

    dim3 grid(NBT, NT2);   // batch fast-varying -> weight tiles shared via L2
    tile_kernel<<<grid, 256, SMEM_TOTAL>>>(label);

    target_kernel<<<(BDIM * 32 + 255) / 256, 256>>>(input, label, weight);
    fin1_kernel<<<BDIM, 128>>>();
    fin2_kernel<<<1, BDIM>>>(out);
}

// round 4
// speedup vs baseline: 5.2781x; 1.0298x over previous
#include <cuda_runtime.h>
#include <cuda_bf16.h>
#include <cstdint>
#include <math.h>

#define BDIM 1024
#define DDIM 512
#define CDIM 100000
#define SCALE 64.0f
#define MARGIN 0.35f
#define TM 128
#define TN 128
#define NT2 ((CDIM + TN - 1) / TN)   // 782 class tiles
#define NBT (BDIM / TM)              // 8 batch tiles

// ---------------- static scratch ---------------------------------------------
__device__ int   g_is64;
__device__ float g_rnx[BDIM];
__device__ float g_rwn[CDIM];
__device__ __nv_bfloat16 g_xb[BDIM * DDIM];
__device__ __nv_bfloat16 g_wb[(size_t)CDIM * DDIM];
__device__ float g_partial[BDIM * NT2];
__device__ float g_tgt[BDIM];
__device__ float g_rowloss[BDIM];

// ---------------- helpers -----------------------------------------------------
__device__ __forceinline__ uint32_t smem_u32(const void* p) {
    uint32_t a;
    asm("{ .reg .u64 t; cvta.to.shared.u64 t, %1; cvt.u32.u64 %0, t; }" : "=r"(a) : "l"(p));
    return a;
}
__device__ __forceinline__ void cpa16(uint32_t dst, const void* src, int pred) {
    int sz = pred ? 16 : 0;
    asm volatile("cp.async.cg.shared.global [%0], [%1], 16, %2;" :: "r"(dst), "l"(src), "r"(sz));
}
#define CP_COMMIT() asm volatile("cp.async.commit_group;" ::: "memory")
#define CP_WAIT1()  asm volatile("cp.async.wait_group 1;" ::: "memory")

#define LDSM4(r0, r1, r2, r3, a) \
    asm volatile("ldmatrix.sync.aligned.m8n8.x4.shared.b16 {%0,%1,%2,%3}, [%4];" \
                 : "=r"(r0), "=r"(r1), "=r"(r2), "=r"(r3) : "r"(a))

#define MMA16816(d, a, b) \
    asm volatile("mma.sync.aligned.m16n8k16.row.col.f32.bf16.bf16.f32 " \
                 "{%0,%1,%2,%3}, {%4,%5,%6,%7}, {%8,%9}, {%0,%1,%2,%3};" \
                 : "+f"((d)[0]), "+f"((d)[1]), "+f"((d)[2]), "+f"((d)[3]) \
                 : "r"((a)[0]), "r"((a)[1]), "r"((a)[2]), "r"((a)[3]), "r"((b)[0]), "r"((b)[1]))

// ---------------- label dtype ------------------------------------------------
__device__ __forceinline__ int get_label(const void* p, int i) {
    if (g_is64) return (int)((const long long*)p)[i];
    return ((const int*)p)[i];
}
__global__ void detect_kernel(const void* __restrict__ lab) {
    __shared__ int ok;
    if (threadIdx.x == 0) ok = 1;
    __syncthreads();
    const long long* q = (const long long*)lab;
    for (int i = threadIdx.x; i < BDIM / 2; i += blockDim.x) {
        long long v = q[i];
        if (v < 0 || v >= (long long)CDIM) ok = 0;
    }
    __syncthreads();
    if (threadIdx.x == 0) g_is64 = ok;
}

// ---------------- normalize + cast to bf16 ------------------------------------
__global__ void norm_cast_kernel(const float* __restrict__ p, int nrows, int which) {
    int w    = (blockIdx.x * blockDim.x + threadIdx.x) >> 5;
    int lane = threadIdx.x & 31;
    if (w >= nrows) return;
    const float4* pr = (const float4*)(p + (long long)w * DDIM);
    float s = 0.f;
    #pragma unroll 4
    for (int k = lane; k < DDIM / 4; k += 32) {
        float4 a = pr[k];
        s += a.x * a.x + a.y * a.y + a.z * a.z + a.w * a.w;
    }
    #pragma unroll
    for (int off = 16; off >= 1; off >>= 1)
        s += __shfl_xor_sync(0xffffffffu, s, off);
    float r = 1.0f / fmaxf(sqrtf(s), 1e-12f);
    if (lane == 0) { if (which) g_rwn[w] = r; else g_rnx[w] = r; }
    __nv_bfloat162* d2 = (__nv_bfloat162*)((which ? g_wb : g_xb) + (long long)w * DDIM);
    const float2* p2 = (const float2*)(p + (long long)w * DDIM);
    #pragma unroll
    for (int j = 0; j < 8; ++j) {
        int e2 = lane * 8 + j;
        float2 v = p2[e2];
        d2[e2] = __floats2bfloat162_rn(v.x * r, v.y * r);
    }
}

// ---------------- fast exp (FFMA pipe) ----------------------------------------
__device__ __forceinline__ float fexp(float x) {
    float tt = x * 1.44269504f;
    float fi = rintf(tt);
    float f  = tt - fi;
    float p  = 1.535336188319500e-4f;
    p = fmaf(p, f, 1.339887440266574e-3f);
    p = fmaf(p, f, 9.618437357674640e-3f);
    p = fmaf(p, f, 5.550332471162809e-2f);
    p = fmaf(p, f, 2.402264791363012e-1f);
    p = fmaf(p, f, 6.931472028550421e-1f);
    p = fmaf(p, f, 1.0f);
    int i = (int)fi;
    return p * __int_as_float((i + 127) << 23);
}

// smem layout (bytes): 3 stages of (A 18432 + B 18432) = 110592,
// labels @110592 (512), redbuf @111104 (2048) -> 113152 total per CTA
#define STAGE_BYTES 36864u
#define SM_LAB 110592
#define SM_RED 111104
#define SMEM_TOTAL 113152

// ---------------- main fused GEMM kernel --------------------------------------
__global__ __launch_bounds__(256, 2) void tile_kernel(const void* __restrict__ label) {
    extern __shared__ char smem[];
    const int t    = threadIdx.x;
    const int wid  = t >> 5;
    const int lane = t & 31;
    const int wm   = wid >> 2;       // 0..1 : m-slice of 64
    const int wn   = wid & 3;        // 0..3 : n-slice of 32
    const int rowBase = blockIdx.x * TM;
    const int colBase = blockIdx.y * TN;
    const uint32_t sb = smem_u32(smem);
    int*   labp = (int*)(smem + SM_LAB);
    float* red  = (float*)(smem + SM_RED);

    if (t < TM) labp[t] = get_label(label, rowBase + t);

    // ---- cp.async tile loaders (each thread: 4 sectors A + 4 sectors B) ----
    const int ldr = t >> 1;          // 0..127 row handled (2 threads per row)
    const int ldc = (t & 1) * 4;     // starting 16B-sector within row (0 or 4)
    const __nv_bfloat16* agp = g_xb + ((long long)(rowBase + ldr) << 9) + (ldc << 3);
    int cgB = colBase + ldr;
    int bpred = cgB < CDIM;
    const __nv_bfloat16* bgp = g_wb + ((long long)(bpred ? cgB : 0) << 9) + (ldc << 3);
    const uint32_t adst = sb + ldr * 144 + ldc * 16;
    const uint32_t bdst = sb + 18432 + ldr * 144 + ldc * 16;

    #define LOAD_CHUNK(kc, stg) do {                                        \
        const __nv_bfloat16* as = agp + ((kc) << 6);                        \
        const __nv_bfloat16* bs = bgp + ((kc) << 6);                        \
        uint32_t ad = adst + (stg) * STAGE_BYTES;                           \
        uint32_t bd = bdst + (stg) * STAGE_BYTES;                           \
        _Pragma("unroll")                                                   \
        for (int s = 0; s < 4; ++s) {                                       \
            cpa16(ad + s * 16, as + s * 8, 1);                              \
            cpa16(bd + s * 16, bs + s * 8, bpred);                          \
        }                                                                   \
        CP_COMMIT();                                                        \
    } while (0)

    LOAD_CHUNK(0, 0);
    LOAD_CHUNK(1, 1);

    // ---- per-lane ldmatrix base addresses ----
    const int aRow = wm * 64 + (lane & 15);
    const int aKof = (lane >> 4) * 8;
    const uint32_t aAddrBase = sb + aRow * 144 + aKof * 2;
    const int g = lane >> 3;
    const int bRow = wn * 32 + ((g >> 1) << 3) + (lane & 7);
    const int bKof = (g & 1) * 8;
    const uint32_t bAddrBase = sb + 18432u + bRow * 144 + bKof * 2;

    float acc[4][4][4];
    #pragma unroll
    for (int mi = 0; mi < 4; ++mi)
        #pragma unroll
        for (int ni = 0; ni < 4; ++ni)
            #pragma unroll
            for (int c = 0; c < 4; ++c) acc[mi][ni][c] = 0.f;

    #pragma unroll 1
    for (int kc = 0; kc < 8; ++kc) {
        const int cs = kc % 3;               // compute stage
        CP_WAIT1();                          // chunk kc complete (in-order retire)
        __syncthreads();                     // all warps done with stage (kc+2)%3's old data
        if (kc + 2 < 8) {
            const int ps = (kc + 2) % 3;
            LOAD_CHUNK(kc + 2, ps);          // 2 chunks in flight during compute
        } else {
            CP_COMMIT();                     // keep group counts consistent
        }
        const uint32_t aB = aAddrBase + cs * STAGE_BYTES;
        const uint32_t bB = bAddrBase + cs * STAGE_BYTES;
        #pragma unroll
        for (int ks = 0; ks < 4; ++ks) {
            uint32_t afr[4][4];
            uint32_t bfr[4][2];
            #pragma unroll
            for (int mi = 0; mi < 4; ++mi)
                LDSM4(afr[mi][0], afr[mi][1], afr[mi][2], afr[mi][3],
                      aB + mi * 16 * 144 + ks * 32);
            #pragma unroll
            for (int p = 0; p < 2; ++p)
                LDSM4(bfr[2 * p][0], bfr[2 * p][1], bfr[2 * p + 1][0], bfr[2 * p + 1][1],
                      bB + p * 16 * 144 + ks * 32);
            #pragma unroll
            for (int mi = 0; mi < 4; ++mi)
                #pragma unroll
                for (int ni = 0; ni < 4; ++ni)
                    MMA16816(acc[mi][ni], afr[mi], bfr[ni]);
        }
    }

    // ---- epilogue: scale, margin, exp, per-row partials ----
    const int groupID = lane >> 2;
    const int tid4    = lane & 3;
    #pragma unroll
    for (int mi = 0; mi < 4; ++mi) {
        #pragma unroll
        for (int half = 0; half < 2; ++half) {
            const int rl  = wm * 64 + mi * 16 + groupID + half * 8;
            const int lab = labp[rl];
            float s = 0.f;
            #pragma unroll
            for (int ni = 0; ni < 4; ++ni) {
                const int c0 = colBase + wn * 32 + ni * 8 + tid4 * 2;
                #pragma unroll
                for (int cc = 0; cc < 2; ++cc) {
                    const int col = c0 + cc;
                    if (col < CDIM) {
                        float x = acc[mi][ni][half * 2 + cc] * SCALE;
                        if (col == lab) x -= SCALE * MARGIN;
                        s += fexp(x);
                    }
                }
            }
            s += __shfl_xor_sync(0xffffffffu, s, 1);
            s += __shfl_xor_sync(0xffffffffu, s, 2);
            if (tid4 == 0) red[rl * 4 + wn] = s;
        }
    }
    __syncthreads();
    if (t < TM) {
        float s = red[t * 4 + 0] + red[t * 4 + 1] + red[t * 4 + 2] + red[t * 4 + 3];
        g_partial[(rowBase + t) * NT2 + blockIdx.y] = s;
    }
}

// ---------------- exact fp32 target logit -------------------------------------
__global__ void target_kernel(const float* __restrict__ input,
                              const void*  __restrict__ label,
                              const float* __restrict__ weight) {
    int w    = (blockIdx.x * blockDim.x + threadIdx.x) >> 5;
    int lane = threadIdx.x & 31;
    if (w >= BDIM) return;
    int lab = get_label(label, w);
    const float4* xr = (const float4*)(input  + (long long)w   * DDIM);
    const float4* wr = (const float4*)(weight + (long long)lab * DDIM);
    float s = 0.f;
    #pragma unroll 4
    for (int k = lane; k < DDIM / 4; k += 32) {
        float4 a = xr[k], b = wr[k];
        s += a.x * b.x + a.y * b.y + a.z * b.z + a.w * b.w;
    }
    #pragma unroll
    for (int off = 16; off >= 1; off >>= 1)
        s += __shfl_xor_sync(0xffffffffu, s, off);
    if (lane == 0)
        g_tgt[w] = SCALE * (s * g_rnx[w] * g_rwn[lab] - MARGIN);
}

// ---------------- per-row logsumexp + loss ------------------------------------
__global__ void fin1_kernel() {
    int r = blockIdx.x;
    float s = 0.f;
    for (int i = threadIdx.x; i < NT2; i += blockDim.x)
        s += g_partial[r * NT2 + i];
    #pragma unroll
    for (int off = 16; off >= 1; off >>= 1)
        s += __shfl_xor_sync(0xffffffffu, s, off);
    __shared__ float sm[4];
    int lane = threadIdx.x & 31, wid = threadIdx.x >> 5;
    if (lane == 0) sm[wid] = s;
    __syncthreads();
    if (threadIdx.x == 0) {
        float tot = sm[0] + sm[1] + sm[2] + sm[3];
        g_rowloss[r] = logf(tot) - g_tgt[r];
    }
}
__global__ void fin2_kernel(float* __restrict__ out) {
    __shared__ float sm[32];
    float s = g_rowloss[threadIdx.x];
    #pragma unroll
    for (int off = 16; off >= 1; off >>= 1)
        s += __shfl_xor_sync(0xffffffffu, s, off);
    int lane = threadIdx.x & 31, wid = threadIdx.x >> 5;
    if (lane == 0) sm[wid] = s;
    __syncthreads();
    if (wid == 0) {
        float v = sm[lane];
        #pragma unroll
        for (int off = 16; off >= 1; off >>= 1)
            v += __shfl_xor_sync(0xffffffffu, v, off);
        if (lane == 0) out[0] = v * (1.0f / (float)BDIM);
    }
}

// ---------------- launch ------------------------------------------------------
extern "C" void kernel_launch(void* const* d_in, const int* in_sizes, int n_in,
                              void* d_out, int out_size) {
    const float* input  = (const float*)d_in[0];
    const void*  label  = d_in[1];
    const float* weight = (const float*)d_in[2];
    float* out = (float*)d_out;

    cudaFuncSetAttribute(tile_kernel, cudaFuncAttributeMaxDynamicSharedMemorySize, SMEM_TOTAL);

    detect_kernel<<<1, 256>>>(label);
    norm_cast_kernel<<<(BDIM * 32 + 255) / 256, 256>>>(input, BDIM, 0);
    norm_cast_kernel<<<(CDIM * 32 + 255) / 256, 256>>>(weight, CDIM, 1);

    dim3 grid(NBT, NT2);   // batch fast-varying -> weight tiles shared via L2
    tile_kernel<<<grid, 256, SMEM_TOTAL>>>(label);

    target_kernel<<<(BDIM * 32 + 255) / 256, 256>>>(input, label, weight);
    fin1_kernel<<<BDIM, 128>>>();
    fin2_kernel<<<1, BDIM>>>(out);
}

// round 5
// speedup vs baseline: 5.3530x; 1.0142x over previous
#include <cuda_runtime.h>
#include <cuda_bf16.h>
#include <cstdint>
#include <math.h>

#define BDIM 1024
#define DDIM 512
#define CDIM 100000
#define SCALE 64.0f
#define MARGIN 0.35f
#define TM 128
#define TN 128
#define NT2 ((CDIM + TN - 1) / TN)   // 782 class tiles
#define NBT (BDIM / TM)              // 8 batch tiles

// ---------------- static scratch ---------------------------------------------
__device__ int   g_is64;
__device__ float g_rnx[BDIM];
__device__ float g_rwn[CDIM];
__device__ __nv_bfloat16 g_xb[BDIM * DDIM];
__device__ __nv_bfloat16 g_wb[(size_t)CDIM * DDIM];
__device__ float g_partial[BDIM * NT2];
__device__ float g_tgt[BDIM];
__device__ float g_rowloss[BDIM];

// ---------------- helpers -----------------------------------------------------
__device__ __forceinline__ uint32_t smem_u32(const void* p) {
    uint32_t a;
    asm("{ .reg .u64 t; cvta.to.shared.u64 t, %1; cvt.u32.u64 %0, t; }" : "=r"(a) : "l"(p));
    return a;
}
__device__ __forceinline__ void cpa16(uint32_t dst, const void* src, int pred) {
    int sz = pred ? 16 : 0;
    asm volatile("cp.async.cg.shared.global [%0], [%1], 16, %2;" :: "r"(dst), "l"(src), "r"(sz));
}
#define CP_COMMIT() asm volatile("cp.async.commit_group;" ::: "memory")
#define CP_WAIT0()  asm volatile("cp.async.wait_group 0;" ::: "memory")

#define LDSM4(r0, r1, r2, r3, a) \
    asm volatile("ldmatrix.sync.aligned.m8n8.x4.shared.b16 {%0,%1,%2,%3}, [%4];" \
                 : "=r"(r0), "=r"(r1), "=r"(r2), "=r"(r3) : "r"(a))

#define MMA16816(d, a, b) \
    asm volatile("mma.sync.aligned.m16n8k16.row.col.f32.bf16.bf16.f32 " \
                 "{%0,%1,%2,%3}, {%4,%5,%6,%7}, {%8,%9}, {%0,%1,%2,%3};" \
                 : "+f"((d)[0]), "+f"((d)[1]), "+f"((d)[2]), "+f"((d)[3]) \
                 : "r"((a)[0]), "r"((a)[1]), "r"((a)[2]), "r"((a)[3]), "r"((b)[0]), "r"((b)[1]))

// ---------------- label dtype ------------------------------------------------
__device__ __forceinline__ int get_label(const void* p, int i) {
    if (g_is64) return (int)((const long long*)p)[i];
    return ((const int*)p)[i];
}
__global__ void detect_kernel(const void* __restrict__ lab) {
    __shared__ int ok;
    if (threadIdx.x == 0) ok = 1;
    __syncthreads();
    const long long* q = (const long long*)lab;
    for (int i = threadIdx.x; i < BDIM / 2; i += blockDim.x) {
        long long v = q[i];
        if (v < 0 || v >= (long long)CDIM) ok = 0;
    }
    __syncthreads();
    if (threadIdx.x == 0) g_is64 = ok;
}

// ---------------- normalize + cast to bf16 ------------------------------------
__global__ void norm_cast_kernel(const float* __restrict__ p, int nrows, int which) {
    int w    = (blockIdx.x * blockDim.x + threadIdx.x) >> 5;
    int lane = threadIdx.x & 31;
    if (w >= nrows) return;
    const float4* pr = (const float4*)(p + (long long)w * DDIM);
    float s = 0.f;
    #pragma unroll 4
    for (int k = lane; k < DDIM / 4; k += 32) {
        float4 a = pr[k];
        s += a.x * a.x + a.y * a.y + a.z * a.z + a.w * a.w;
    }
    #pragma unroll
    for (int off = 16; off >= 1; off >>= 1)
        s += __shfl_xor_sync(0xffffffffu, s, off);
    float r = 1.0f / fmaxf(sqrtf(s), 1e-12f);
    if (lane == 0) { if (which) g_rwn[w] = r; else g_rnx[w] = r; }
    __nv_bfloat162* d2 = (__nv_bfloat162*)((which ? g_wb : g_xb) + (long long)w * DDIM);
    const float2* p2 = (const float2*)(p + (long long)w * DDIM);
    #pragma unroll
    for (int j = 0; j < 8; ++j) {
        int e2 = lane * 8 + j;
        float2 v = p2[e2];
        d2[e2] = __floats2bfloat162_rn(v.x * r, v.y * r);
    }
}

// ---------------- fast exp (FFMA pipe) ----------------------------------------
__device__ __forceinline__ float fexp(float x) {
    float tt = x * 1.44269504f;
    float fi = rintf(tt);
    float f  = tt - fi;
    float p  = 1.535336188319500e-4f;
    p = fmaf(p, f, 1.339887440266574e-3f);
    p = fmaf(p, f, 9.618437357674640e-3f);
    p = fmaf(p, f, 5.550332471162809e-2f);
    p = fmaf(p, f, 2.402264791363012e-1f);
    p = fmaf(p, f, 6.931472028550421e-1f);
    p = fmaf(p, f, 1.0f);
    int i = (int)fi;
    return p * __int_as_float((i + 127) << 23);
}

// smem: 2 stages of (A 18432 + B 18432) = 73728, labels @73728, red @74240
#define STAGE_BYTES 36864u
#define SM_LAB 73728
#define SM_RED 74240
#define SMEM_TOTAL 76288

// ---------------- main fused GEMM kernel --------------------------------------
__global__ __launch_bounds__(256, 2) void tile_kernel(const void* __restrict__ label) {
    extern __shared__ char smem[];
    const int t    = threadIdx.x;
    const int wid  = t >> 5;
    const int lane = t & 31;
    const int wm   = wid >> 2;       // 0..1 : m-slice of 64
    const int wn   = wid & 3;        // 0..3 : n-slice of 32
    const int rowBase = blockIdx.x * TM;
    const int colBase = blockIdx.y * TN;
    const uint32_t sb = smem_u32(smem);
    int*   labp = (int*)(smem + SM_LAB);
    float* red  = (float*)(smem + SM_RED);

    if (t < TM) labp[t] = get_label(label, rowBase + t);

    // ---- cp.async tile loaders ----
    const int ldr = t >> 1;
    const int ldc = (t & 1) * 4;
    const __nv_bfloat16* agp = g_xb + ((long long)(rowBase + ldr) << 9) + (ldc << 3);
    int cgB = colBase + ldr;
    int bpred = cgB < CDIM;
    const __nv_bfloat16* bgp = g_wb + ((long long)(bpred ? cgB : 0) << 9) + (ldc << 3);
    const uint32_t adst = sb + ldr * 144 + ldc * 16;
    const uint32_t bdst = sb + 18432 + ldr * 144 + ldc * 16;

    #define LOAD_CHUNK(kc, stg) do {                                        \
        const __nv_bfloat16* as = agp + ((kc) << 6);                        \
        const __nv_bfloat16* bs = bgp + ((kc) << 6);                        \
        uint32_t ad = adst + (stg) * STAGE_BYTES;                           \
        uint32_t bd = bdst + (stg) * STAGE_BYTES;                           \
        _Pragma("unroll")                                                   \
        for (int s = 0; s < 4; ++s) {                                       \
            cpa16(ad + s * 16, as + s * 8, 1);                              \
            cpa16(bd + s * 16, bs + s * 8, bpred);                          \
        }                                                                   \
        CP_COMMIT();                                                        \
    } while (0)

    // ---- per-lane ldmatrix base addresses ----
    const int aRow = wm * 64 + (lane & 15);
    const int aKof = (lane >> 4) * 8;
    const uint32_t aAddrBase = sb + aRow * 144 + aKof * 2;
    const int g = lane >> 3;
    const int bRow = wn * 32 + ((g >> 1) << 3) + (lane & 7);
    const int bKof = (g & 1) * 8;
    const uint32_t bAddrBase = sb + 18432u + bRow * 144 + bKof * 2;

    // fragment double buffers
    uint32_t afr[2][4][4];
    uint32_t bfr[2][4][2];
    #define LDFRAGS(buf, stg, ksv) do {                                     \
        uint32_t aB_ = aAddrBase + (stg) * STAGE_BYTES + (ksv) * 32;        \
        uint32_t bB_ = bAddrBase + (stg) * STAGE_BYTES + (ksv) * 32;        \
        _Pragma("unroll")                                                   \
        for (int mi = 0; mi < 4; ++mi)                                      \
            LDSM4(afr[buf][mi][0], afr[buf][mi][1], afr[buf][mi][2],        \
                  afr[buf][mi][3], aB_ + mi * 16 * 144);                    \
        _Pragma("unroll")                                                   \
        for (int p = 0; p < 2; ++p)                                         \
            LDSM4(bfr[buf][2 * p][0], bfr[buf][2 * p][1],                   \
                  bfr[buf][2 * p + 1][0], bfr[buf][2 * p + 1][1],           \
                  bB_ + p * 16 * 144);                                      \
    } while (0)

    float acc[4][4][4];
    #pragma unroll
    for (int mi = 0; mi < 4; ++mi)
        #pragma unroll
        for (int ni = 0; ni < 4; ++ni)
            #pragma unroll
            for (int c = 0; c < 4; ++c) acc[mi][ni][c] = 0.f;

    // ---- prologue ----
    LOAD_CHUNK(0, 0);
    CP_WAIT0();
    __syncthreads();
    LDFRAGS(0, 0, 0);
    LOAD_CHUNK(1, 1);

    // ---- mainloop: frag prefetch hides LDSM latency under 16 MMAs ----
    #pragma unroll 1
    for (int kc = 0; kc < 8; ++kc) {
        const int stg = kc & 1;
        #pragma unroll
        for (int ks = 0; ks < 4; ++ks) {
            const int cur = ks & 1;
            const int nxt = cur ^ 1;
            if (ks < 3) {
                LDFRAGS(nxt, stg, ks + 1);
            } else if (kc < 7) {
                CP_WAIT0();          // chunk kc+1 resident in stage stg^1
                __syncthreads();     // all warps done LDSM-ing stage stg
                if (kc < 6) LOAD_CHUNK(kc + 2, stg);
                LDFRAGS(nxt, stg ^ 1, 0);
            }
            #pragma unroll
            for (int mi = 0; mi < 4; ++mi)
                #pragma unroll
                for (int ni = 0; ni < 4; ++ni)
                    MMA16816(acc[mi][ni], afr[cur][mi], bfr[cur][ni]);
        }
    }

    // ---- epilogue: scale, margin, exp, per-row partials ----
    const int groupID = lane >> 2;
    const int tid4    = lane & 3;
    #pragma unroll
    for (int mi = 0; mi < 4; ++mi) {
        #pragma unroll
        for (int half = 0; half < 2; ++half) {
            const int rl  = wm * 64 + mi * 16 + groupID + half * 8;
            const int lab = labp[rl];
            float s = 0.f;
            #pragma unroll
            for (int ni = 0; ni < 4; ++ni) {
                const int c0 = colBase + wn * 32 + ni * 8 + tid4 * 2;
                #pragma unroll
                for (int cc = 0; cc < 2; ++cc) {
                    const int col = c0 + cc;
                    if (col < CDIM) {
                        float x = acc[mi][ni][half * 2 + cc] * SCALE;
                        if (col == lab) x -= SCALE * MARGIN;
                        s += fexp(x);
                    }
                }
            }
            s += __shfl_xor_sync(0xffffffffu, s, 1);
            s += __shfl_xor_sync(0xffffffffu, s, 2);
            if (tid4 == 0) red[rl * 4 + wn] = s;
        }
    }
    __syncthreads();
    if (t < TM) {
        float s = red[t * 4 + 0] + red[t * 4 + 1] + red[t * 4 + 2] + red[t * 4 + 3];
        g_partial[(rowBase + t) * NT2 + blockIdx.y] = s;
    }
}

// ---------------- exact fp32 target logit -------------------------------------
__global__ void target_kernel(const float* __restrict__ input,
                              const void*  __restrict__ label,
                              const float* __restrict__ weight) {
    int w    = (blockIdx.x * blockDim.x + threadIdx.x) >> 5;
    int lane = threadIdx.x & 31;
    if (w >= BDIM) return;
    int lab = get_label(label, w);
    const float4* xr = (const float4*)(input  + (long long)w   * DDIM);
    const float4* wr = (const float4*)(weight + (long long)lab * DDIM);
    float s = 0.f;
    #pragma unroll 4
    for (int k = lane; k < DDIM / 4; k += 32) {
        float4 a = xr[k], b = wr[k];
        s += a.x * b.x + a.y * b.y + a.z * b.z + a.w * b.w;
    }
    #pragma unroll
    for (int off = 16; off >= 1; off >>= 1)
        s += __shfl_xor_sync(0xffffffffu, s, off);
    if (lane == 0)
        g_tgt[w] = SCALE * (s * g_rnx[w] * g_rwn[lab] - MARGIN);
}

// ---------------- per-row logsumexp + loss ------------------------------------
__global__ void fin1_kernel() {
    int r = blockIdx.x;
    float s = 0.f;
    for (int i = threadIdx.x; i < NT2; i += blockDim.x)
        s += g_partial[r * NT2 + i];
    #pragma unroll
    for (int off = 16; off >= 1; off >>= 1)
        s += __shfl_xor_sync(0xffffffffu, s, off);
    __shared__ float sm[4];
    int lane = threadIdx.x & 31, wid = threadIdx.x >> 5;
    if (lane == 0) sm[wid] = s;
    __syncthreads();
    if (threadIdx.x == 0) {
        float tot = sm[0] + sm[1] + sm[2] + sm[3];
        g_rowloss[r] = logf(tot) - g_tgt[r];
    }
}
__global__ void fin2_kernel(float* __restrict__ out) {
    __shared__ float sm[32];
    float s = g_rowloss[threadIdx.x];
    #pragma unroll
    for (int off = 16; off >= 1; off >>= 1)
        s += __shfl_xor_sync(0xffffffffu, s, off);
    int lane = threadIdx.x & 31, wid = threadIdx.x >> 5;
    if (lane == 0) sm[wid] = s;
    __syncthreads();
    if (wid == 0) {
        float v = sm[lane];
        #pragma unroll
        for (int off = 16; off >= 1; off >>= 1)
            v += __shfl_xor_sync(0xffffffffu, v, off);
        if (lane == 0) out[0] = v * (1.0f / (float)BDIM);
    }
}

// ---------------- launch ------------------------------------------------------
extern "C" void kernel_launch(void* const* d_in, const int* in_sizes, int n_in,
                              void* d_out, int out_size) {
    const float* input  = (const float*)d_in[0];
    const void*  label  = d_in[1];
    const float* weight = (const float*)d_in[2];
    float* out = (float*)d_out;

    cudaFuncSetAttribute(tile_kernel, cudaFuncAttributeMaxDynamicSharedMemorySize, SMEM_TOTAL);

    detect_kernel<<<1, 256>>>(label);
    norm_cast_kernel<<<(BDIM * 32 + 255) / 256, 256>>>(input, BDIM, 0);
    norm_cast_kernel<<<(CDIM * 32 + 255) / 256, 256>>>(weight, CDIM, 1);

    dim3 grid(NBT, NT2);   // batch fast-varying -> weight tiles shared via L2
    tile_kernel<<<grid, 256, SMEM_TOTAL>>>(label);

    target_kernel<<<(BDIM * 32 + 255) / 256, 256>>>(input, label, weight);
    fin1_kernel<<<BDIM, 128>>>();
    fin2_kernel<<<1, BDIM>>>(out);
}

// round 7
// speedup vs baseline: 5.4649x; 1.0209x over previous
#include <cuda_runtime.h>
#include <cuda_bf16.h>
#include <cstdint>
#include <math.h>

#define BDIM 1024
#define DDIM 512
#define CDIM 100000
#define SCALE 64.0f
#define MARGIN 0.35f
#define TM 64
#define TN 128
#define NT2 ((CDIM + TN - 1) / TN)   // 782 class tiles
#define NBT (BDIM / TM)              // 16 batch tiles

// ---------------- static scratch ---------------------------------------------
__device__ int   g_is64;
__device__ float g_rnx[BDIM];
__device__ float g_rwn[CDIM];
__device__ __nv_bfloat16 g_xb[BDIM * DDIM];
__device__ __nv_bfloat16 g_wb[(size_t)CDIM * DDIM];
__device__ float g_partial[BDIM * NT2];
__device__ float g_tgt[BDIM];
__device__ float g_rowloss[BDIM];

// ---------------- helpers -----------------------------------------------------
__device__ __forceinline__ uint32_t smem_u32(const void* p) {
    uint32_t a;
    asm("{ .reg .u64 t; cvta.to.shared.u64 t, %1; cvt.u32.u64 %0, t; }" : "=r"(a) : "l"(p));
    return a;
}
__device__ __forceinline__ void cpa16(uint32_t dst, const void* src, int pred) {
    int sz = pred ? 16 : 0;
    asm volatile("cp.async.cg.shared.global [%0], [%1], 16, %2;" :: "r"(dst), "l"(src), "r"(sz));
}
#define CP_COMMIT() asm volatile("cp.async.commit_group;" ::: "memory")
#define CP_WAIT1()  asm volatile("cp.async.wait_group 1;" ::: "memory")

#define LDSM4(r0, r1, r2, r3, a) \
    asm volatile("ldmatrix.sync.aligned.m8n8.x4.shared.b16 {%0,%1,%2,%3}, [%4];" \
                 : "=r"(r0), "=r"(r1), "=r"(r2), "=r"(r3) : "r"(a))

#define MMA16816(d, a, b) \
    asm volatile("mma.sync.aligned.m16n8k16.row.col.f32.bf16.bf16.f32 " \
                 "{%0,%1,%2,%3}, {%4,%5,%6,%7}, {%8,%9}, {%0,%1,%2,%3};" \
                 : "+f"((d)[0]), "+f"((d)[1]), "+f"((d)[2]), "+f"((d)[3]) \
                 : "r"((a)[0]), "r"((a)[1]), "r"((a)[2]), "r"((a)[3]), "r"((b)[0]), "r"((b)[1]))

// ---------------- label dtype ------------------------------------------------
__device__ __forceinline__ int get_label(const void* p, int i) {
    if (g_is64) return (int)((const long long*)p)[i];
    return ((const int*)p)[i];
}
__global__ void detect_kernel(const void* __restrict__ lab) {
    __shared__ int ok;
    if (threadIdx.x == 0) ok = 1;
    __syncthreads();
    const long long* q = (const long long*)lab;
    for (int i = threadIdx.x; i < BDIM / 2; i += blockDim.x) {
        long long v = q[i];
        if (v < 0 || v >= (long long)CDIM) ok = 0;
    }
    __syncthreads();
    if (threadIdx.x == 0) g_is64 = ok;
}

// ---------------- normalize + cast to bf16 (coalesced) ------------------------
__global__ void norm_cast_kernel(const float* __restrict__ p, int nrows, int which) {
    int w    = (blockIdx.x * blockDim.x + threadIdx.x) >> 5;
    int lane = threadIdx.x & 31;
    if (w >= nrows) return;
    const float4* pr = (const float4*)(p + (long long)w * DDIM);
    float s = 0.f;
    #pragma unroll 4
    for (int k = lane; k < DDIM / 4; k += 32) {
        float4 a = pr[k];
        s += a.x * a.x + a.y * a.y + a.z * a.z + a.w * a.w;
    }
    #pragma unroll
    for (int off = 16; off >= 1; off >>= 1)
        s += __shfl_xor_sync(0xffffffffu, s, off);
    float r = 1.0f / fmaxf(sqrtf(s), 1e-12f);
    if (lane == 0) { if (which) g_rwn[w] = r; else g_rnx[w] = r; }
    __nv_bfloat162* d2 = (__nv_bfloat162*)((which ? g_wb : g_xb) + (long long)w * DDIM);
    const float2* p2 = (const float2*)(p + (long long)w * DDIM);
    #pragma unroll
    for (int j = 0; j < 8; ++j) {
        int e2 = j * 32 + lane;
        float2 v = p2[e2];
        d2[e2] = __floats2bfloat162_rn(v.x * r, v.y * r);
    }
}

// ---------------- fast exp (FFMA pipe) ----------------------------------------
__device__ __forceinline__ float fexp(float x) {
    float tt = x * 1.44269504f;
    float fi = rintf(tt);
    float f  = tt - fi;
    float p  = 1.535336188319500e-4f;
    p = fmaf(p, f, 1.339887440266574e-3f);
    p = fmaf(p, f, 9.618437357674640e-3f);
    p = fmaf(p, f, 5.550332471162809e-2f);
    p = fmaf(p, f, 2.402264791363012e-1f);
    p = fmaf(p, f, 6.931472028550421e-1f);
    p = fmaf(p, f, 1.0f);
    int i = (int)fi;
    return p * __int_as_float((i + 127) << 23);
}

// smem: stage = A(64*144=9216) + B(128*144=18432) = 27648; 2 stages = 55296
// labels @55296 (256B), red @55552 (1024B) -> 56576 per CTA
#define STAGE_BYTES 27648u
#define SM_BOFF 9216u
#define SM_LAB 55296
#define SM_RED 55552
#define SMEM_TOTAL 56576

// ---------------- main fused GEMM kernel --------------------------------------
__global__ __launch_bounds__(256, 3) void tile_kernel(const void* __restrict__ label) {
    extern __shared__ char smem[];
    const int t    = threadIdx.x;
    const int wid  = t >> 5;
    const int lane = t & 31;
    const int wm   = wid >> 2;       // 0..1 : m-slice of 32
    const int wn   = wid & 3;        // 0..3 : n-slice of 32
    const int rowBase = blockIdx.x * TM;
    const int colBase = blockIdx.y * TN;
    const uint32_t sb = smem_u32(smem);
    int*   labp = (int*)(smem + SM_LAB);
    float* red  = (float*)(smem + SM_RED);

    if (t < TM) labp[t] = get_label(label, rowBase + t);

    // ---- cp.async tile loaders: each thread 2 A-sectors + 4 B-sectors ----
    const int arow  = t >> 2;        // 0..63
    const int ascol = (t & 3) * 2;   // 0,2,4,6
    const __nv_bfloat16* agp = g_xb + ((long long)(rowBase + arow) << 9) + (ascol << 3);
    const uint32_t adst = sb + arow * 144 + ascol * 16;

    const int brow  = t >> 1;        // 0..127
    const int bscol = (t & 1) * 4;   // 0,4
    int cgB = colBase + brow;
    int bpred = cgB < CDIM;
    const __nv_bfloat16* bgp = g_wb + ((long long)(bpred ? cgB : 0) << 9) + (bscol << 3);
    const uint32_t bdst = sb + SM_BOFF + brow * 144 + bscol * 16;

    #define LOAD_CHUNK(kc, stg) do {                                        \
        const __nv_bfloat16* as = agp + ((kc) << 6);                        \
        const __nv_bfloat16* bs = bgp + ((kc) << 6);                        \
        uint32_t ad = adst + (stg) * STAGE_BYTES;                           \
        uint32_t bd = bdst + (stg) * STAGE_BYTES;                           \
        cpa16(ad,      as,      1);                                         \
        cpa16(ad + 16, as + 8,  1);                                         \
        _Pragma("unroll")                                                   \
        for (int s = 0; s < 4; ++s)                                         \
            cpa16(bd + s * 16, bs + s * 8, bpred);                          \
        CP_COMMIT();                                                        \
    } while (0)

    LOAD_CHUNK(0, 0);
    LOAD_CHUNK(1, 1);

    // ---- per-lane ldmatrix base addresses (warp tile 32x32) ----
    const uint32_t aAddrBase = sb + (wm * 32 + (lane & 15)) * 144 + ((lane >> 4) * 8) * 2;
    const int g = lane >> 3;
    const uint32_t bAddrBase = sb + SM_BOFF
        + (wn * 32 + ((g >> 1) << 3) + (lane & 7)) * 144 + ((g & 1) * 8) * 2;

    float acc[2][4][4];
    #pragma unroll
    for (int mi = 0; mi < 2; ++mi)
        #pragma unroll
        for (int ni = 0; ni < 4; ++ni)
            #pragma unroll
            for (int c = 0; c < 4; ++c) acc[mi][ni][c] = 0.f;

    #pragma unroll 1
    for (int kc = 0; kc < 8; ++kc) {
        const int stg = kc & 1;
        CP_WAIT1();
        __syncthreads();
        const uint32_t aB = aAddrBase + stg * STAGE_BYTES;
        const uint32_t bB = bAddrBase + stg * STAGE_BYTES;
        #pragma unroll
        for (int ks = 0; ks < 4; ++ks) {
            uint32_t afr[2][4];
            uint32_t bfr[4][2];
            #pragma unroll
            for (int mi = 0; mi < 2; ++mi)
                LDSM4(afr[mi][0], afr[mi][1], afr[mi][2], afr[mi][3],
                      aB + mi * 16 * 144 + ks * 32);
            #pragma unroll
            for (int p = 0; p < 2; ++p)
                LDSM4(bfr[2 * p][0], bfr[2 * p][1], bfr[2 * p + 1][0], bfr[2 * p + 1][1],
                      bB + p * 16 * 144 + ks * 32);
            #pragma unroll
            for (int mi = 0; mi < 2; ++mi)
                #pragma unroll
                for (int ni = 0; ni < 4; ++ni)
                    MMA16816(acc[mi][ni], afr[mi], bfr[ni]);
        }
        __syncthreads();
        if (kc + 2 < 8) LOAD_CHUNK(kc + 2, stg);
        else CP_COMMIT();
    }

    // ---- epilogue: scale, margin, exp, per-row partials ----
    const int groupID = lane >> 2;
    const int tid4    = lane & 3;
    #pragma unroll
    for (int mi = 0; mi < 2; ++mi) {
        #pragma unroll
        for (int half = 0; half < 2; ++half) {
            const int rl  = wm * 32 + mi * 16 + groupID + half * 8;
            const int lab = labp[rl];
            float s = 0.f;
            #pragma unroll
            for (int ni = 0; ni < 4; ++ni) {
                const int c0 = colBase + wn * 32 + ni * 8 + tid4 * 2;
                #pragma unroll
                for (int cc = 0; cc < 2; ++cc) {
                    const int col = c0 + cc;
                    if (col < CDIM) {
                        float x = acc[mi][ni][half * 2 + cc] * SCALE;
                        if (col == lab) x -= SCALE * MARGIN;
                        s += fexp(x);
                    }
                }
            }
            s += __shfl_xor_sync(0xffffffffu, s, 1);
            s += __shfl_xor_sync(0xffffffffu, s, 2);
            if (tid4 == 0) red[rl * 4 + wn] = s;
        }
    }
    __syncthreads();
    if (t < TM) {
        float s = red[t * 4 + 0] + red[t * 4 + 1] + red[t * 4 + 2] + red[t * 4 + 3];
        g_partial[(rowBase + t) * NT2 + blockIdx.y] = s;
    }
}

// ---------------- exact fp32 target logit -------------------------------------
__global__ void target_kernel(const float* __restrict__ input,
                              const void*  __restrict__ label,
                              const float* __restrict__ weight) {
    int w    = (blockIdx.x * blockDim.x + threadIdx.x) >> 5;
    int lane = threadIdx.x & 31;
    if (w >= BDIM) return;
    int lab = get_label(label, w);
    const float4* xr = (const float4*)(input  + (long long)w   * DDIM);
    const float4* wr = (const float4*)(weight + (long long)lab * DDIM);
    float s = 0.f;
    #pragma unroll 4
    for (int k = lane; k < DDIM / 4; k += 32) {
        float4 a = xr[k], b = wr[k];
        s += a.x * b.x + a.y * b.y + a.z * b.z + a.w * b.w;
    }
    #pragma unroll
    for (int off = 16; off >= 1; off >>= 1)
        s += __shfl_xor_sync(0xffffffffu, s, off);
    if (lane == 0)
        g_tgt[w] = SCALE * (s * g_rnx[w] * g_rwn[lab] - MARGIN);
}

// ---------------- per-row logsumexp + loss ------------------------------------
__global__ void fin1_kernel() {
    int r = blockIdx.x;
    float s = 0.f;
    for (int i = threadIdx.x; i < NT2; i += blockDim.x)
        s += g_partial[r * NT2 + i];
    #pragma unroll
    for (int off = 16; off >= 1; off >>= 1)
        s += __shfl_xor_sync(0xffffffffu, s, off);
    __shared__ float sm[4];
    int lane = threadIdx.x & 31, wid = threadIdx.x >> 5;
    if (lane == 0) sm[wid] = s;
    __syncthreads();
    if (threadIdx.x == 0) {
        float tot = sm[0] + sm[1] + sm[2] + sm[3];
        g_rowloss[r] = logf(tot) - g_tgt[r];
    }
}
__global__ void fin2_kernel(float* __restrict__ out) {
    __shared__ float sm[32];
    float s = g_rowloss[threadIdx.x];
    #pragma unroll
    for (int off = 16; off >= 1; off >>= 1)
        s += __shfl_xor_sync(0xffffffffu, s, off);
    int lane = threadIdx.x & 31, wid = threadIdx.x >> 5;
    if (lane == 0) sm[wid] = s;
    __syncthreads();
    if (wid == 0) {
        float v = sm[lane];
        #pragma unroll
        for (int off = 16; off >= 1; off >>= 1)
            v += __shfl_xor_sync(0xffffffffu, v, off);
        if (lane == 0) out[0] = v * (1.0f / (float)BDIM);
    }
}

// ---------------- launch ------------------------------------------------------
extern "C" void kernel_launch(void* const* d_in, const int* in_sizes, int n_in,
                              void* d_out, int out_size) {
    const float* input  = (const float*)d_in[0];
    const void*  label  = d_in[1];
    const float* weight = (const float*)d_in[2];
    float* out = (float*)d_out;

    cudaFuncSetAttribute(tile_kernel, cudaFuncAttributeMaxDynamicSharedMemorySize, SMEM_TOTAL);

    detect_kernel<<<1, 256>>>(label);
    norm_cast_kernel<<<(BDIM * 32 + 255) / 256, 256>>>(input, BDIM, 0);
    norm_cast_kernel<<<(CDIM * 32 + 255) / 256, 256>>>(weight, CDIM, 1);

    dim3 grid(NBT, NT2);   // batch fast-varying -> weight tiles shared via L2
    tile_kernel<<<grid, 256, SMEM_TOTAL>>>(label);

    target_kernel<<<(BDIM * 32 + 255) / 256, 256>>>(input, label, weight);
    fin1_kernel<<<BDIM, 128>>>();
    fin2_kernel<<<1, BDIM>>>(out);
}

// round 8
// speedup vs baseline: 8.5245x; 1.5599x over previous
#include <cuda_runtime.h>
#include <cuda_bf16.h>
#include <cstdint>
#include <math.h>

#define BDIM 1024
#define DDIM 512
#define CDIM 100000
#define SCALE 64.0f
#define MARGIN 0.35f
#define TM 64
#define TN 128
#define NT2 ((CDIM + TN - 1) / TN)   // 782 class tiles
#define NBT (BDIM / TM)              // 16 batch tiles

// ---------------- static scratch ---------------------------------------------
__device__ int    g_is64;
__device__ float  g_rnx[BDIM];
__device__ float  g_rwn[CDIM];
__device__ float  g_fx[BDIM];                 // per-row dequant factor (input)
__device__ float  g_fw[CDIM];                 // per-row dequant factor (weight)
__device__ int8_t g_xq[BDIM * DDIM];
__device__ int8_t g_wq[(size_t)CDIM * DDIM];
__device__ float  g_partial[BDIM * NT2];
__device__ float  g_tgt[BDIM];
__device__ float  g_rowloss[BDIM];

// ---------------- helpers -----------------------------------------------------
__device__ __forceinline__ uint32_t smem_u32(const void* p) {
    uint32_t a;
    asm("{ .reg .u64 t; cvta.to.shared.u64 t, %1; cvt.u32.u64 %0, t; }" : "=r"(a) : "l"(p));
    return a;
}
__device__ __forceinline__ void cpa16(uint32_t dst, const void* src, int pred) {
    int sz = pred ? 16 : 0;
    asm volatile("cp.async.cg.shared.global [%0], [%1], 16, %2;" :: "r"(dst), "l"(src), "r"(sz));
}
#define CP_COMMIT() asm volatile("cp.async.commit_group;" ::: "memory")
#define CP_WAIT1()  asm volatile("cp.async.wait_group 1;" ::: "memory")

#define LDSM4(r0, r1, r2, r3, a) \
    asm volatile("ldmatrix.sync.aligned.m8n8.x4.shared.b16 {%0,%1,%2,%3}, [%4];" \
                 : "=r"(r0), "=r"(r1), "=r"(r2), "=r"(r3) : "r"(a))

// s8 x s8 -> s32, m16n8k32
#define IMMA16832(d, a, b) \
    asm volatile("mma.sync.aligned.m16n8k32.row.col.s32.s8.s8.s32 " \
                 "{%0,%1,%2,%3}, {%4,%5,%6,%7}, {%8,%9}, {%0,%1,%2,%3};" \
                 : "+r"((d)[0]), "+r"((d)[1]), "+r"((d)[2]), "+r"((d)[3]) \
                 : "r"((a)[0]), "r"((a)[1]), "r"((a)[2]), "r"((a)[3]), "r"((b)[0]), "r"((b)[1]))

// ---------------- label dtype ------------------------------------------------
__device__ __forceinline__ int get_label(const void* p, int i) {
    if (g_is64) return (int)((const long long*)p)[i];
    return ((const int*)p)[i];
}
__global__ void detect_kernel(const void* __restrict__ lab) {
    __shared__ int ok;
    if (threadIdx.x == 0) ok = 1;
    __syncthreads();
    const long long* q = (const long long*)lab;
    for (int i = threadIdx.x; i < BDIM / 2; i += blockDim.x) {
        long long v = q[i];
        if (v < 0 || v >= (long long)CDIM) ok = 0;
    }
    __syncthreads();
    if (threadIdx.x == 0) g_is64 = ok;
}

// ---------------- normalize + quantize to int8 --------------------------------
__global__ void norm_quant_kernel(const float* __restrict__ p, int nrows, int which) {
    int w    = (blockIdx.x * blockDim.x + threadIdx.x) >> 5;
    int lane = threadIdx.x & 31;
    if (w >= nrows) return;
    const float4* pr = (const float4*)(p + (long long)w * DDIM);
    float4 v[4];
    float ss = 0.f, ma = 0.f;
    #pragma unroll
    for (int j = 0; j < 4; ++j) {
        v[j] = pr[j * 32 + lane];
        ss += v[j].x * v[j].x + v[j].y * v[j].y + v[j].z * v[j].z + v[j].w * v[j].w;
        ma = fmaxf(ma, fmaxf(fmaxf(fabsf(v[j].x), fabsf(v[j].y)),
                             fmaxf(fabsf(v[j].z), fabsf(v[j].w))));
    }
    #pragma unroll
    for (int off = 16; off >= 1; off >>= 1) {
        ss += __shfl_xor_sync(0xffffffffu, ss, off);
        ma = fmaxf(ma, __shfl_xor_sync(0xffffffffu, ma, off));
    }
    float r  = 1.0f / fmaxf(sqrtf(ss), 1e-12f);
    float qs = 127.0f / fmaxf(ma, 1e-30f);          // quant scale (raw -> int8)
    float f  = ma * r * (1.0f / 127.0f);            // dequant factor (int -> normalized)
    if (lane == 0) {
        if (which) { g_rwn[w] = r; g_fw[w] = f; }
        else       { g_rnx[w] = r; g_fx[w] = f; }
    }
    uint32_t* dst = (uint32_t*)((which ? g_wq : g_xq) + (long long)w * DDIM);
    #pragma unroll
    for (int j = 0; j < 4; ++j) {
        int q0 = __float2int_rn(v[j].x * qs);
        int q1 = __float2int_rn(v[j].y * qs);
        int q2 = __float2int_rn(v[j].z * qs);
        int q3 = __float2int_rn(v[j].w * qs);
        uint32_t pk = (uint32_t)(q0 & 0xff) | ((uint32_t)(q1 & 0xff) << 8) |
                      ((uint32_t)(q2 & 0xff) << 16) | ((uint32_t)(q3 & 0xff) << 24);
        dst[j * 32 + lane] = pk;
    }
}

// ---------------- fast exp (FFMA pipe) ----------------------------------------
__device__ __forceinline__ float fexp(float x) {
    float tt = x * 1.44269504f;
    float fi = rintf(tt);
    float f  = tt - fi;
    float p  = 1.535336188319500e-4f;
    p = fmaf(p, f, 1.339887440266574e-3f);
    p = fmaf(p, f, 9.618437357674640e-3f);
    p = fmaf(p, f, 5.550332471162809e-2f);
    p = fmaf(p, f, 2.402264791363012e-1f);
    p = fmaf(p, f, 6.931472028550421e-1f);
    p = fmaf(p, f, 1.0f);
    int i = (int)fi;
    return p * __int_as_float((i + 127) << 23);
}

// smem: stage = A(64*144=9216) + B(128*144=18432) = 27648; 2 stages = 55296
// labels @55296 (256), qx @55552 (256), qw @55808 (512), red @56320 (1024) -> 57344
#define STAGE_BYTES 27648u
#define SM_BOFF 9216u
#define SM_LAB 55296
#define SM_QX  55552
#define SM_QW  55808
#define SM_RED 56320
#define SMEM_TOTAL 57344

// ---------------- main fused int8 GEMM kernel ---------------------------------
__global__ __launch_bounds__(256, 3) void tile_kernel(const void* __restrict__ label) {
    extern __shared__ char smem[];
    const int t    = threadIdx.x;
    const int wid  = t >> 5;
    const int lane = t & 31;
    const int wm   = wid >> 2;       // 0..1 : m-slice of 32
    const int wn   = wid & 3;        // 0..3 : n-slice of 32
    const int rowBase = blockIdx.x * TM;
    const int colBase = blockIdx.y * TN;
    const uint32_t sb = smem_u32(smem);
    int*   labp = (int*)(smem + SM_LAB);
    float* qxS  = (float*)(smem + SM_QX);
    float* qwS  = (float*)(smem + SM_QW);
    float* red  = (float*)(smem + SM_RED);

    if (t < TM) {
        labp[t] = get_label(label, rowBase + t);
        qxS[t]  = g_fx[rowBase + t] * SCALE;   // fold logit scale into row factor
    }
    if (t >= 128) {
        int c = t - 128;
        int cg = colBase + c;
        qwS[c] = (cg < CDIM) ? g_fw[cg] : 0.f;
    }

    // ---- cp.async tile loaders (chunk = K 128 bytes) ----
    const int arow = t >> 2;         // 0..63
    const int asec = (t & 3) * 2;    // sectors 0,2,4,6 (2 x 16B per thread)
    const int8_t* agp = g_xq + ((long long)(rowBase + arow) << 9) + (asec << 4);
    const uint32_t adst = sb + arow * 144 + asec * 16;

    const int brow = t >> 1;         // 0..127
    const int bsec = (t & 1) * 4;    // sectors 0 or 4 (4 x 16B per thread)
    int cgB = colBase + brow;
    int bpred = cgB < CDIM;
    const int8_t* bgp = g_wq + ((long long)(bpred ? cgB : 0) << 9) + (bsec << 4);
    const uint32_t bdst = sb + SM_BOFF + brow * 144 + bsec * 16;

    #define LOAD_CHUNK(kc, stg) do {                                        \
        const int8_t* as = agp + ((kc) << 7);                               \
        const int8_t* bs = bgp + ((kc) << 7);                               \
        uint32_t ad = adst + (stg) * STAGE_BYTES;                           \
        uint32_t bd = bdst + (stg) * STAGE_BYTES;                           \
        cpa16(ad,      as,      1);                                         \
        cpa16(ad + 16, as + 16, 1);                                         \
        _Pragma("unroll")                                                   \
        for (int s = 0; s < 4; ++s)                                         \
            cpa16(bd + s * 16, bs + s * 16, bpred);                         \
        CP_COMMIT();                                                        \
    } while (0)

    LOAD_CHUNK(0, 0);
    LOAD_CHUNK(1, 1);

    // ---- per-lane ldmatrix base addresses (int8: 16B k-offsets) ----
    const uint32_t aAddrBase = sb + (wm * 32 + (lane & 15)) * 144 + (lane >> 4) * 16;
    const int g = lane >> 3;
    const uint32_t bAddrBase = sb + SM_BOFF
        + (wn * 32 + ((g >> 1) << 3) + (lane & 7)) * 144 + (g & 1) * 16;

    int acc[2][4][4];
    #pragma unroll
    for (int mi = 0; mi < 2; ++mi)
        #pragma unroll
        for (int ni = 0; ni < 4; ++ni)
            #pragma unroll
            for (int c = 0; c < 4; ++c) acc[mi][ni][c] = 0;

    #pragma unroll 1
    for (int kc = 0; kc < 4; ++kc) {
        const int stg = kc & 1;
        CP_WAIT1();
        __syncthreads();
        const uint32_t aB = aAddrBase + stg * STAGE_BYTES;
        const uint32_t bB = bAddrBase + stg * STAGE_BYTES;
        #pragma unroll
        for (int ks = 0; ks < 4; ++ks) {      // 4 k-steps of 32 bytes
            uint32_t afr[2][4];
            uint32_t bfr[4][2];
            #pragma unroll
            for (int mi = 0; mi < 2; ++mi)
                LDSM4(afr[mi][0], afr[mi][1], afr[mi][2], afr[mi][3],
                      aB + mi * 16 * 144 + ks * 32);
            #pragma unroll
            for (int p = 0; p < 2; ++p)
                LDSM4(bfr[2 * p][0], bfr[2 * p][1], bfr[2 * p + 1][0], bfr[2 * p + 1][1],
                      bB + p * 16 * 144 + ks * 32);
            #pragma unroll
            for (int mi = 0; mi < 2; ++mi)
                #pragma unroll
                for (int ni = 0; ni < 4; ++ni)
                    IMMA16832(acc[mi][ni], afr[mi], bfr[ni]);
        }
        __syncthreads();
        if (kc + 2 < 4) LOAD_CHUNK(kc + 2, stg);
        else CP_COMMIT();
    }

    // ---- epilogue: dequant, scale, margin, exp, per-row partials ----
    const int groupID = lane >> 2;
    const int tid4    = lane & 3;
    #pragma unroll
    for (int mi = 0; mi < 2; ++mi) {
        #pragma unroll
        for (int half = 0; half < 2; ++half) {
            const int rl  = wm * 32 + mi * 16 + groupID + half * 8;
            const int lab = labp[rl];
            const float fx = qxS[rl];
            float s = 0.f;
            #pragma unroll
            for (int ni = 0; ni < 4; ++ni) {
                const int cl0 = wn * 32 + ni * 8 + tid4 * 2;
                #pragma unroll
                for (int cc = 0; cc < 2; ++cc) {
                    const int col = colBase + cl0 + cc;
                    if (col < CDIM) {
                        float x = (float)acc[mi][ni][half * 2 + cc] * (fx * qwS[cl0 + cc]);
                        if (col == lab) x -= SCALE * MARGIN;
                        s += fexp(x);
                    }
                }
            }
            s += __shfl_xor_sync(0xffffffffu, s, 1);
            s += __shfl_xor_sync(0xffffffffu, s, 2);
            if (tid4 == 0) red[rl * 4 + wn] = s;
        }
    }
    __syncthreads();
    if (t < TM) {
        float s = red[t * 4 + 0] + red[t * 4 + 1] + red[t * 4 + 2] + red[t * 4 + 3];
        g_partial[(rowBase + t) * NT2 + blockIdx.y] = s;
    }
}

// ---------------- exact fp32 target logit -------------------------------------
__global__ void target_kernel(const float* __restrict__ input,
                              const void*  __restrict__ label,
                              const float* __restrict__ weight) {
    int w    = (blockIdx.x * blockDim.x + threadIdx.x) >> 5;
    int lane = threadIdx.x & 31;
    if (w >= BDIM) return;
    int lab = get_label(label, w);
    const float4* xr = (const float4*)(input  + (long long)w   * DDIM);
    const float4* wr = (const float4*)(weight + (long long)lab * DDIM);
    float s = 0.f;
    #pragma unroll 4
    for (int k = lane; k < DDIM / 4; k += 32) {
        float4 a = xr[k], b = wr[k];
        s += a.x * b.x + a.y * b.y + a.z * b.z + a.w * b.w;
    }
    #pragma unroll
    for (int off = 16; off >= 1; off >>= 1)
        s += __shfl_xor_sync(0xffffffffu, s, off);
    if (lane == 0)
        g_tgt[w] = SCALE * (s * g_rnx[w] * g_rwn[lab] - MARGIN);
}

// ---------------- per-row logsumexp + loss ------------------------------------
__global__ void fin1_kernel() {
    int r = blockIdx.x;
    float s = 0.f;
    for (int i = threadIdx.x; i < NT2; i += blockDim.x)
        s += g_partial[r * NT2 + i];
    #pragma unroll
    for (int off = 16; off >= 1; off >>= 1)
        s += __shfl_xor_sync(0xffffffffu, s, off);
    __shared__ float sm[4];
    int lane = threadIdx.x & 31, wid = threadIdx.x >> 5;
    if (lane == 0) sm[wid] = s;
    __syncthreads();
    if (threadIdx.x == 0) {
        float tot = sm[0] + sm[1] + sm[2] + sm[3];
        g_rowloss[r] = logf(tot) - g_tgt[r];
    }
}
__global__ void fin2_kernel(float* __restrict__ out) {
    __shared__ float sm[32];
    float s = g_rowloss[threadIdx.x];
    #pragma unroll
    for (int off = 16; off >= 1; off >>= 1)
        s += __shfl_xor_sync(0xffffffffu, s, off);
    int lane = threadIdx.x & 31, wid = threadIdx.x >> 5;
    if (lane == 0) sm[wid] = s;
    __syncthreads();
    if (wid == 0) {
        float v = sm[lane];
        #pragma unroll
        for (int off = 16; off >= 1; off >>= 1)
            v += __shfl_xor_sync(0xffffffffu, v, off);
        if (lane == 0) out[0] = v * (1.0f / (float)BDIM);
    }
}

// ---------------- launch ------------------------------------------------------
extern "C" void kernel_launch(void* const* d_in, const int* in_sizes, int n_in,
                              void* d_out, int out_size) {
    const float* input  = (const float*)d_in[0];
    const void*  label  = d_in[1];
    const float* weight = (const float*)d_in[2];
    float* out = (float*)d_out;

    cudaFuncSetAttribute(tile_kernel, cudaFuncAttributeMaxDynamicSharedMemorySize, SMEM_TOTAL);

    detect_kernel<<<1, 256>>>(label);
    norm_quant_kernel<<<(BDIM * 32 + 255) / 256, 256>>>(input, BDIM, 0);
    norm_quant_kernel<<<(CDIM * 32 + 255) / 256, 256>>>(weight, CDIM, 1);

    dim3 grid(NBT, NT2);   // batch fast-varying -> weight tiles shared via L2
    tile_kernel<<<grid, 256, SMEM_TOTAL>>>(label);

    target_kernel<<<(BDIM * 32 + 255) / 256, 256>>>(input, label, weight);
    fin1_kernel<<<BDIM, 128>>>();
    fin2_kernel<<<1, BDIM>>>(out);
}

// round 9
// speedup vs baseline: 9.7414x; 1.1427x over previous
#include <cuda_runtime.h>
#include <cuda_bf16.h>
#include <cstdint>
#include <math.h>

#define BDIM 1024
#define DDIM 512
#define CDIM 100000
#define SCALE 64.0f
#define MARGIN 0.35f
#define L2E 1.44269504f
#define TM 64
#define TN 128
#define NT2 ((CDIM + TN - 1) / TN)   // 782 class tiles
#define NBT (BDIM / TM)              // 16 batch tiles

// ---------------- static scratch ---------------------------------------------
__device__ int    g_is64;
__device__ float  g_rnx[BDIM];
__device__ float  g_rwn[CDIM];
__device__ float  g_fx[BDIM];
__device__ float  g_fw[CDIM];
__device__ int8_t g_xq[BDIM * DDIM];
__device__ int8_t g_wq[(size_t)CDIM * DDIM];
__device__ float  g_partial[BDIM * NT2];
__device__ float  g_tgt[BDIM];
__device__ float  g_xlq[BDIM];               // quantized label logit (pre-margin)
__device__ float  g_rowloss[BDIM];

// ---------------- helpers -----------------------------------------------------
__device__ __forceinline__ uint32_t smem_u32(const void* p) {
    uint32_t a;
    asm("{ .reg .u64 t; cvta.to.shared.u64 t, %1; cvt.u32.u64 %0, t; }" : "=r"(a) : "l"(p));
    return a;
}
__device__ __forceinline__ void cpa16(uint32_t dst, const void* src, int pred) {
    int sz = pred ? 16 : 0;
    asm volatile("cp.async.cg.shared.global [%0], [%1], 16, %2;" :: "r"(dst), "l"(src), "r"(sz));
}
#define CP_COMMIT() asm volatile("cp.async.commit_group;" ::: "memory")
#define CP_WAIT1()  asm volatile("cp.async.wait_group 1;" ::: "memory")

#define LDSM4(r0, r1, r2, r3, a) \
    asm volatile("ldmatrix.sync.aligned.m8n8.x4.shared.b16 {%0,%1,%2,%3}, [%4];" \
                 : "=r"(r0), "=r"(r1), "=r"(r2), "=r"(r3) : "r"(a))

#define IMMA16832(d, a, b) \
    asm volatile("mma.sync.aligned.m16n8k32.row.col.s32.s8.s8.s32 " \
                 "{%0,%1,%2,%3}, {%4,%5,%6,%7}, {%8,%9}, {%0,%1,%2,%3};" \
                 : "+r"((d)[0]), "+r"((d)[1]), "+r"((d)[2]), "+r"((d)[3]) \
                 : "r"((a)[0]), "r"((a)[1]), "r"((a)[2]), "r"((a)[3]), "r"((b)[0]), "r"((b)[1]))

// ---------------- fast exp2: input pre-scaled by log2(e) ----------------------
// 2^tt for |tt| <= 92; magic-number round, deg-5 poly on [-0.5, 0.5]
__device__ __forceinline__ float fexp2(float tt) {
    float z  = tt + 12582912.0f;     // 1.5 * 2^23 magic: low bits = round(tt)
    float zf = z - 12582912.0f;
    float f  = tt - zf;              // f in [-0.5, 0.5]
    float p  = 1.339887440266574e-3f;
    p = fmaf(p, f, 9.618437357674640e-3f);
    p = fmaf(p, f, 5.550332471162809e-2f);
    p = fmaf(p, f, 2.402264791363012e-1f);
    p = fmaf(p, f, 6.931472028550421e-1f);
    p = fmaf(p, f, 1.0f);
    uint32_t sc = (__float_as_uint(z) + 0xB4C0007Fu) << 23;   // (i+127)<<23
    return p * __uint_as_float(sc);
}

// ---------------- label dtype ------------------------------------------------
__device__ __forceinline__ int get_label(const void* p, int i) {
    if (g_is64) return (int)((const long long*)p)[i];
    return ((const int*)p)[i];
}
__global__ void detect_kernel(const void* __restrict__ lab) {
    __shared__ int ok;
    if (threadIdx.x == 0) ok = 1;
    __syncthreads();
    const long long* q = (const long long*)lab;
    for (int i = threadIdx.x; i < BDIM / 2; i += blockDim.x) {
        long long v = q[i];
        if (v < 0 || v >= (long long)CDIM) ok = 0;
    }
    __syncthreads();
    if (threadIdx.x == 0) g_is64 = ok;
}

// ---------------- normalize + quantize to int8 --------------------------------
__global__ void norm_quant_kernel(const float* __restrict__ p, int nrows, int which) {
    int w    = (blockIdx.x * blockDim.x + threadIdx.x) >> 5;
    int lane = threadIdx.x & 31;
    if (w >= nrows) return;
    const float4* pr = (const float4*)(p + (long long)w * DDIM);
    float4 v[4];
    float ss = 0.f, ma = 0.f;
    #pragma unroll
    for (int j = 0; j < 4; ++j) {
        v[j] = pr[j * 32 + lane];
        ss += v[j].x * v[j].x + v[j].y * v[j].y + v[j].z * v[j].z + v[j].w * v[j].w;
        ma = fmaxf(ma, fmaxf(fmaxf(fabsf(v[j].x), fabsf(v[j].y)),
                             fmaxf(fabsf(v[j].z), fabsf(v[j].w))));
    }
    #pragma unroll
    for (int off = 16; off >= 1; off >>= 1) {
        ss += __shfl_xor_sync(0xffffffffu, ss, off);
        ma = fmaxf(ma, __shfl_xor_sync(0xffffffffu, ma, off));
    }
    float r  = 1.0f / fmaxf(sqrtf(ss), 1e-12f);
    float qs = 127.0f / fmaxf(ma, 1e-30f);
    float f  = ma * r * (1.0f / 127.0f);
    if (lane == 0) {
        if (which) { g_rwn[w] = r; g_fw[w] = f; }
        else       { g_rnx[w] = r; g_fx[w] = f; }
    }
    uint32_t* dst = (uint32_t*)((which ? g_wq : g_xq) + (long long)w * DDIM);
    #pragma unroll
    for (int j = 0; j < 4; ++j) {
        int q0 = __float2int_rn(v[j].x * qs);
        int q1 = __float2int_rn(v[j].y * qs);
        int q2 = __float2int_rn(v[j].z * qs);
        int q3 = __float2int_rn(v[j].w * qs);
        uint32_t pk = (uint32_t)(q0 & 0xff) | ((uint32_t)(q1 & 0xff) << 8) |
                      ((uint32_t)(q2 & 0xff) << 16) | ((uint32_t)(q3 & 0xff) << 24);
        dst[j * 32 + lane] = pk;
    }
}

// smem: stage = A(64*144=9216) + B(128*144=18432) = 27648; 2 stages = 55296
// qx @55296 (256), qw @55552 (512), red @56064 (1024) -> 57088
#define STAGE_BYTES 27648u
#define SM_BOFF 9216u
#define SM_QX  55296
#define SM_QW  55552
#define SM_RED 56064
#define SMEM_TOTAL 57088

// ---------------- main fused int8 GEMM kernel ---------------------------------
__global__ __launch_bounds__(256, 3) void tile_kernel() {
    extern __shared__ char smem[];
    const int t    = threadIdx.x;
    const int wid  = t >> 5;
    const int lane = t & 31;
    const int wm   = wid >> 2;       // 0..1 : m-slice of 32
    const int wn   = wid & 3;        // 0..3 : n-slice of 32
    const int rowBase = blockIdx.x * TM;
    const int colBase = blockIdx.y * TN;
    const uint32_t sb = smem_u32(smem);
    float* qxS = (float*)(smem + SM_QX);
    float* qwS = (float*)(smem + SM_QW);
    float* red = (float*)(smem + SM_RED);

    if (t < TM) qxS[t] = g_fx[rowBase + t] * (SCALE * L2E);  // fold S*log2e
    if (t >= 128) {
        int c = t - 128;
        int cg = colBase + c;
        qwS[c] = (cg < CDIM) ? g_fw[cg] : 0.f;
    }

    // ---- cp.async tile loaders (chunk = K 128 bytes) ----
    const int arow = t >> 2;
    const int asec = (t & 3) * 2;
    const int8_t* agp = g_xq + ((long long)(rowBase + arow) << 9) + (asec << 4);
    const uint32_t adst = sb + arow * 144 + asec * 16;

    const int brow = t >> 1;
    const int bsec = (t & 1) * 4;
    int cgB = colBase + brow;
    int bpred = cgB < CDIM;
    const int8_t* bgp = g_wq + ((long long)(bpred ? cgB : 0) << 9) + (bsec << 4);
    const uint32_t bdst = sb + SM_BOFF + brow * 144 + bsec * 16;

    #define LOAD_CHUNK(kc, stg) do {                                        \
        const int8_t* as = agp + ((kc) << 7);                               \
        const int8_t* bs = bgp + ((kc) << 7);                               \
        uint32_t ad = adst + (stg) * STAGE_BYTES;                           \
        uint32_t bd = bdst + (stg) * STAGE_BYTES;                           \
        cpa16(ad,      as,      1);                                         \
        cpa16(ad + 16, as + 16, 1);                                         \
        _Pragma("unroll")                                                   \
        for (int s = 0; s < 4; ++s)                                         \
            cpa16(bd + s * 16, bs + s * 16, bpred);                         \
        CP_COMMIT();                                                        \
    } while (0)

    LOAD_CHUNK(0, 0);
    LOAD_CHUNK(1, 1);

    const uint32_t aAddrBase = sb + (wm * 32 + (lane & 15)) * 144 + (lane >> 4) * 16;
    const int g = lane >> 3;
    const uint32_t bAddrBase = sb + SM_BOFF
        + (wn * 32 + ((g >> 1) << 3) + (lane & 7)) * 144 + (g & 1) * 16;

    int acc[2][4][4];
    #pragma unroll
    for (int mi = 0; mi < 2; ++mi)
        #pragma unroll
        for (int ni = 0; ni < 4; ++ni)
            #pragma unroll
            for (int c = 0; c < 4; ++c) acc[mi][ni][c] = 0;

    #pragma unroll 1
    for (int kc = 0; kc < 4; ++kc) {
        const int stg = kc & 1;
        CP_WAIT1();
        __syncthreads();
        const uint32_t aB = aAddrBase + stg * STAGE_BYTES;
        const uint32_t bB = bAddrBase + stg * STAGE_BYTES;
        #pragma unroll
        for (int ks = 0; ks < 4; ++ks) {
            uint32_t afr[2][4];
            uint32_t bfr[4][2];
            #pragma unroll
            for (int mi = 0; mi < 2; ++mi)
                LDSM4(afr[mi][0], afr[mi][1], afr[mi][2], afr[mi][3],
                      aB + mi * 16 * 144 + ks * 32);
            #pragma unroll
            for (int p = 0; p < 2; ++p)
                LDSM4(bfr[2 * p][0], bfr[2 * p][1], bfr[2 * p + 1][0], bfr[2 * p + 1][1],
                      bB + p * 16 * 144 + ks * 32);
            #pragma unroll
            for (int mi = 0; mi < 2; ++mi)
                #pragma unroll
                for (int ni = 0; ni < 4; ++ni)
                    IMMA16832(acc[mi][ni], afr[mi], bfr[ni]);
        }
        __syncthreads();
        if (kc + 2 < 4) LOAD_CHUNK(kc + 2, stg);
        else CP_COMMIT();
    }

    // ---- epilogue: dequant -> 2^tt -> per-row partials (no margin here) ----
    const int groupID = lane >> 2;
    const int tid4    = lane & 3;
    float qwr[8];
    #pragma unroll
    for (int ni = 0; ni < 4; ++ni) {
        qwr[2 * ni]     = qwS[wn * 32 + ni * 8 + tid4 * 2];
        qwr[2 * ni + 1] = qwS[wn * 32 + ni * 8 + tid4 * 2 + 1];
    }
    const bool fullTile = (colBase + TN) <= CDIM;
    #pragma unroll
    for (int mi = 0; mi < 2; ++mi) {
        #pragma unroll
        for (int half = 0; half < 2; ++half) {
            const int rl  = wm * 32 + mi * 16 + groupID + half * 8;
            const float fxr = qxS[rl];
            float fq[8];
            #pragma unroll
            for (int c = 0; c < 8; ++c) fq[c] = fxr * qwr[c];
            float s0 = 0.f, s1 = 0.f;
            if (fullTile) {
                #pragma unroll
                for (int ni = 0; ni < 4; ++ni) {
                    float fa0 = (float)acc[mi][ni][half * 2 + 0];
                    float fa1 = (float)acc[mi][ni][half * 2 + 1];
                    s0 += fexp2(fa0 * fq[2 * ni]);
                    s1 += fexp2(fa1 * fq[2 * ni + 1]);
                }
            } else {
                #pragma unroll
                for (int ni = 0; ni < 4; ++ni) {
                    #pragma unroll
                    for (int cc = 0; cc < 2; ++cc) {
                        const int col = colBase + wn * 32 + ni * 8 + tid4 * 2 + cc;
                        if (col < CDIM) {
                            float fa = (float)acc[mi][ni][half * 2 + cc];
                            s0 += fexp2(fa * fq[2 * ni + cc]);
                        }
                    }
                }
            }
            float s = s0 + s1;
            s += __shfl_xor_sync(0xffffffffu, s, 1);
            s += __shfl_xor_sync(0xffffffffu, s, 2);
            if (tid4 == 0) red[rl * 4 + wn] = s;
        }
    }
    __syncthreads();
    if (t < TM) {
        float s = red[t * 4 + 0] + red[t * 4 + 1] + red[t * 4 + 2] + red[t * 4 + 3];
        g_partial[(rowBase + t) * NT2 + blockIdx.y] = s;
    }
}

// ------ exact fp32 target logit + quantized label logit (for margin fixup) ----
__global__ void target_kernel(const float* __restrict__ input,
                              const void*  __restrict__ label,
                              const float* __restrict__ weight) {
    int w    = (blockIdx.x * blockDim.x + threadIdx.x) >> 5;
    int lane = threadIdx.x & 31;
    if (w >= BDIM) return;
    int lab = get_label(label, w);
    const float4* xr = (const float4*)(input  + (long long)w   * DDIM);
    const float4* wr = (const float4*)(weight + (long long)lab * DDIM);
    float s = 0.f;
    #pragma unroll 4
    for (int k = lane; k < DDIM / 4; k += 32) {
        float4 a = xr[k], b = wr[k];
        s += a.x * b.x + a.y * b.y + a.z * b.z + a.w * b.w;
    }
    const int* xqi = (const int*)(g_xq + ((long long)w   << 9));
    const int* wqi = (const int*)(g_wq + ((long long)lab << 9));
    int id = 0;
    #pragma unroll 4
    for (int k = lane; k < DDIM / 4; k += 32)
        id = __dp4a(xqi[k], wqi[k], id);
    #pragma unroll
    for (int off = 16; off >= 1; off >>= 1) {
        s  += __shfl_xor_sync(0xffffffffu, s, off);
        id += __shfl_xor_sync(0xffffffffu, id, off);
    }
    if (lane == 0) {
        g_tgt[w] = SCALE * (s * g_rnx[w] * g_rwn[lab] - MARGIN);
        g_xlq[w] = (float)id * g_fx[w] * g_fw[lab] * SCALE;
    }
}

// ---------------- per-row logsumexp + margin fixup + loss ---------------------
__global__ void fin1_kernel() {
    int r = blockIdx.x;
    float s = 0.f;
    for (int i = threadIdx.x; i < NT2; i += blockDim.x)
        s += g_partial[r * NT2 + i];
    #pragma unroll
    for (int off = 16; off >= 1; off >>= 1)
        s += __shfl_xor_sync(0xffffffffu, s, off);
    __shared__ float sm[4];
    int lane = threadIdx.x & 31, wid = threadIdx.x >> 5;
    if (lane == 0) sm[wid] = s;
    __syncthreads();
    if (threadIdx.x == 0) {
        float tot = sm[0] + sm[1] + sm[2] + sm[3];
        float xlq = g_xlq[r];
        // swap unmargined label term (as summed in tile) for margined one
        tot = tot - fexp2(xlq * L2E) + fexp2((xlq - SCALE * MARGIN) * L2E);
        g_rowloss[r] = logf(tot) - g_tgt[r];
    }
}
__global__ void fin2_kernel(float* __restrict__ out) {
    __shared__ float sm[32];
    float s = g_rowloss[threadIdx.x];
    #pragma unroll
    for (int off = 16; off >= 1; off >>= 1)
        s += __shfl_xor_sync(0xffffffffu, s, off);
    int lane = threadIdx.x & 31, wid = threadIdx.x >> 5;
    if (lane == 0) sm[wid] = s;
    __syncthreads();
    if (wid == 0) {
        float v = sm[lane];
        #pragma unroll
        for (int off = 16; off >= 1; off >>= 1)
            v += __shfl_xor_sync(0xffffffffu, v, off);
        if (lane == 0) out[0] = v * (1.0f / (float)BDIM);
    }
}

// ---------------- launch ------------------------------------------------------
extern "C" void kernel_launch(void* const* d_in, const int* in_sizes, int n_in,
                              void* d_out, int out_size) {
    const float* input  = (const float*)d_in[0];
    const void*  label  = d_in[1];
    const float* weight = (const float*)d_in[2];
    float* out = (float*)d_out;

    cudaFuncSetAttribute(tile_kernel, cudaFuncAttributeMaxDynamicSharedMemorySize, SMEM_TOTAL);

    detect_kernel<<<1, 256>>>(label);
    norm_quant_kernel<<<(BDIM * 32 + 255) / 256, 256>>>(input, BDIM, 0);
    norm_quant_kernel<<<(CDIM * 32 + 255) / 256, 256>>>(weight, CDIM, 1);

    dim3 grid(NBT, NT2);   // batch fast-varying -> weight tiles shared via L2
    tile_kernel<<<grid, 256, SMEM_TOTAL>>>();

    target_kernel<<<(BDIM * 32 + 255) / 256, 256>>>(input, label, weight);
    fin1_kernel<<<BDIM, 128>>>();
    fin2_kernel<<<1, BDIM>>>(out);
}

// round 10
// speedup vs baseline: 9.8639x; 1.0126x over previous
#include <cuda_runtime.h>
#include <cuda_bf16.h>
#include <cstdint>
#include <math.h>

#define BDIM 1024
#define DDIM 512
#define CDIM 100000
#define SCALE 64.0f
#define MARGIN 0.35f
#define L2E 1.44269504f
#define TM 64
#define TN 128
#define NT2 ((CDIM + TN - 1) / TN)   // 782 class tiles
#define NBT (BDIM / TM)              // 16 batch tiles

// ---------------- static scratch ---------------------------------------------
__device__ int    g_is64;
__device__ float  g_rnx[BDIM];
__device__ float  g_rwn[CDIM];
__device__ float  g_fx[BDIM];
__device__ float  g_fw[CDIM];
__device__ int8_t g_xq[BDIM * DDIM];
__device__ int8_t g_wq[(size_t)CDIM * DDIM];
__device__ float  g_partial[BDIM * NT2];
__device__ float  g_tgt[BDIM];
__device__ float  g_fix[BDIM];               // margin fixup: e^(margined) - e^(plain)
__device__ float  g_rowloss[BDIM];

// ---------------- helpers -----------------------------------------------------
__device__ __forceinline__ uint32_t smem_u32(const void* p) {
    uint32_t a;
    asm("{ .reg .u64 t; cvta.to.shared.u64 t, %1; cvt.u32.u64 %0, t; }" : "=r"(a) : "l"(p));
    return a;
}
__device__ __forceinline__ void cpa16(uint32_t dst, const void* src, int pred) {
    int sz = pred ? 16 : 0;
    asm volatile("cp.async.cg.shared.global [%0], [%1], 16, %2;" :: "r"(dst), "l"(src), "r"(sz));
}
#define CP_COMMIT() asm volatile("cp.async.commit_group;" ::: "memory")
#define CP_WAIT1()  asm volatile("cp.async.wait_group 1;" ::: "memory")

#define LDSM4(r0, r1, r2, r3, a) \
    asm volatile("ldmatrix.sync.aligned.m8n8.x4.shared.b16 {%0,%1,%2,%3}, [%4];" \
                 : "=r"(r0), "=r"(r1), "=r"(r2), "=r"(r3) : "r"(a))

#define IMMA16832(d, a, b) \
    asm volatile("mma.sync.aligned.m16n8k32.row.col.s32.s8.s8.s32 " \
                 "{%0,%1,%2,%3}, {%4,%5,%6,%7}, {%8,%9}, {%0,%1,%2,%3};" \
                 : "+r"((d)[0]), "+r"((d)[1]), "+r"((d)[2]), "+r"((d)[3]) \
                 : "r"((a)[0]), "r"((a)[1]), "r"((a)[2]), "r"((a)[3]), "r"((b)[0]), "r"((b)[1]))

// ---------------- MUFU-backed 2^x (single SASS instruction) -------------------
__device__ __forceinline__ float ex2(float tt) {
    float r;
    asm("ex2.approx.f32 %0, %1;" : "=f"(r) : "f"(tt));
    return r;
}

// ---------------- label dtype ------------------------------------------------
__device__ __forceinline__ int get_label(const void* p, int i) {
    if (g_is64) return (int)((const long long*)p)[i];
    return ((const int*)p)[i];
}
__global__ void detect_kernel(const void* __restrict__ lab) {
    __shared__ int ok;
    if (threadIdx.x == 0) ok = 1;
    __syncthreads();
    const long long* q = (const long long*)lab;
    for (int i = threadIdx.x; i < BDIM / 2; i += blockDim.x) {
        long long v = q[i];
        if (v < 0 || v >= (long long)CDIM) ok = 0;
    }
    __syncthreads();
    if (threadIdx.x == 0) g_is64 = ok;
}

// ---------------- normalize + quantize to int8 --------------------------------
__global__ void norm_quant_kernel(const float* __restrict__ p, int nrows, int which) {
    int w    = (blockIdx.x * blockDim.x + threadIdx.x) >> 5;
    int lane = threadIdx.x & 31;
    if (w >= nrows) return;
    const float4* pr = (const float4*)(p + (long long)w * DDIM);
    float4 v[4];
    float ss = 0.f, ma = 0.f;
    #pragma unroll
    for (int j = 0; j < 4; ++j) {
        v[j] = pr[j * 32 + lane];
        ss += v[j].x * v[j].x + v[j].y * v[j].y + v[j].z * v[j].z + v[j].w * v[j].w;
        ma = fmaxf(ma, fmaxf(fmaxf(fabsf(v[j].x), fabsf(v[j].y)),
                             fmaxf(fabsf(v[j].z), fabsf(v[j].w))));
    }
    #pragma unroll
    for (int off = 16; off >= 1; off >>= 1) {
        ss += __shfl_xor_sync(0xffffffffu, ss, off);
        ma = fmaxf(ma, __shfl_xor_sync(0xffffffffu, ma, off));
    }
    float r  = 1.0f / fmaxf(sqrtf(ss), 1e-12f);
    float qs = 127.0f / fmaxf(ma, 1e-30f);
    float f  = ma * r * (1.0f / 127.0f);
    if (lane == 0) {
        if (which) { g_rwn[w] = r; g_fw[w] = f; }
        else       { g_rnx[w] = r; g_fx[w] = f; }
    }
    uint32_t* dst = (uint32_t*)((which ? g_wq : g_xq) + (long long)w * DDIM);
    #pragma unroll
    for (int j = 0; j < 4; ++j) {
        int q0 = __float2int_rn(v[j].x * qs);
        int q1 = __float2int_rn(v[j].y * qs);
        int q2 = __float2int_rn(v[j].z * qs);
        int q3 = __float2int_rn(v[j].w * qs);
        uint32_t pk = (uint32_t)(q0 & 0xff) | ((uint32_t)(q1 & 0xff) << 8) |
                      ((uint32_t)(q2 & 0xff) << 16) | ((uint32_t)(q3 & 0xff) << 24);
        dst[j * 32 + lane] = pk;
    }
}

// smem: stage = A(64*144=9216) + B(128*144=18432) = 27648; 2 stages = 55296
// qx @55296 (256), qw @55552 (512), red @56064 (1024) -> 57088
#define STAGE_BYTES 27648u
#define SM_BOFF 9216u
#define SM_QX  55296
#define SM_QW  55552
#define SM_RED 56064
#define SMEM_TOTAL 57088

// ---------------- main fused int8 GEMM kernel ---------------------------------
__global__ __launch_bounds__(256, 3) void tile_kernel() {
    extern __shared__ char smem[];
    const int t    = threadIdx.x;
    const int wid  = t >> 5;
    const int lane = t & 31;
    const int wm   = wid >> 2;       // 0..1 : m-slice of 32
    const int wn   = wid & 3;        // 0..3 : n-slice of 32
    const int rowBase = blockIdx.x * TM;
    const int colBase = blockIdx.y * TN;
    const uint32_t sb = smem_u32(smem);
    float* qxS = (float*)(smem + SM_QX);
    float* qwS = (float*)(smem + SM_QW);
    float* red = (float*)(smem + SM_RED);

    if (t < TM) qxS[t] = g_fx[rowBase + t] * (SCALE * L2E);  // fold S*log2e
    if (t >= 128) {
        int c = t - 128;
        int cg = colBase + c;
        qwS[c] = (cg < CDIM) ? g_fw[cg] : 0.f;
    }

    // ---- cp.async tile loaders (chunk = K 128 bytes) ----
    const int arow = t >> 2;
    const int asec = (t & 3) * 2;
    const int8_t* agp = g_xq + ((long long)(rowBase + arow) << 9) + (asec << 4);
    const uint32_t adst = sb + arow * 144 + asec * 16;

    const int brow = t >> 1;
    const int bsec = (t & 1) * 4;
    int cgB = colBase + brow;
    int bpred = cgB < CDIM;
    const int8_t* bgp = g_wq + ((long long)(bpred ? cgB : 0) << 9) + (bsec << 4);
    const uint32_t bdst = sb + SM_BOFF + brow * 144 + bsec * 16;

    #define LOAD_CHUNK(kc, stg) do {                                        \
        const int8_t* as = agp + ((kc) << 7);                               \
        const int8_t* bs = bgp + ((kc) << 7);                               \
        uint32_t ad = adst + (stg) * STAGE_BYTES;                           \
        uint32_t bd = bdst + (stg) * STAGE_BYTES;                           \
        cpa16(ad,      as,      1);                                         \
        cpa16(ad + 16, as + 16, 1);                                         \
        _Pragma("unroll")                                                   \
        for (int s = 0; s < 4; ++s)                                         \
            cpa16(bd + s * 16, bs + s * 16, bpred);                         \
        CP_COMMIT();                                                        \
    } while (0)

    LOAD_CHUNK(0, 0);
    LOAD_CHUNK(1, 1);

    const uint32_t aAddrBase = sb + (wm * 32 + (lane & 15)) * 144 + (lane >> 4) * 16;
    const int g = lane >> 3;
    const uint32_t bAddrBase = sb + SM_BOFF
        + (wn * 32 + ((g >> 1) << 3) + (lane & 7)) * 144 + (g & 1) * 16;

    int acc[2][4][4];
    #pragma unroll
    for (int mi = 0; mi < 2; ++mi)
        #pragma unroll
        for (int ni = 0; ni < 4; ++ni)
            #pragma unroll
            for (int c = 0; c < 4; ++c) acc[mi][ni][c] = 0;

    #pragma unroll 1
    for (int kc = 0; kc < 4; ++kc) {
        const int stg = kc & 1;
        CP_WAIT1();
        __syncthreads();
        const uint32_t aB = aAddrBase + stg * STAGE_BYTES;
        const uint32_t bB = bAddrBase + stg * STAGE_BYTES;
        #pragma unroll
        for (int ks = 0; ks < 4; ++ks) {
            uint32_t afr[2][4];
            uint32_t bfr[4][2];
            #pragma unroll
            for (int mi = 0; mi < 2; ++mi)
                LDSM4(afr[mi][0], afr[mi][1], afr[mi][2], afr[mi][3],
                      aB + mi * 16 * 144 + ks * 32);
            #pragma unroll
            for (int p = 0; p < 2; ++p)
                LDSM4(bfr[2 * p][0], bfr[2 * p][1], bfr[2 * p + 1][0], bfr[2 * p + 1][1],
                      bB + p * 16 * 144 + ks * 32);
            #pragma unroll
            for (int mi = 0; mi < 2; ++mi)
                #pragma unroll
                for (int ni = 0; ni < 4; ++ni)
                    IMMA16832(acc[mi][ni], afr[mi], bfr[ni]);
        }
        __syncthreads();
        if (kc + 2 < 4) LOAD_CHUNK(kc + 2, stg);
        else CP_COMMIT();
    }

    // ---- epilogue: dequant -> MUFU 2^tt -> per-row partials (no margin) ----
    const int groupID = lane >> 2;
    const int tid4    = lane & 3;
    float qwr[8];
    #pragma unroll
    for (int ni = 0; ni < 4; ++ni) {
        qwr[2 * ni]     = qwS[wn * 32 + ni * 8 + tid4 * 2];
        qwr[2 * ni + 1] = qwS[wn * 32 + ni * 8 + tid4 * 2 + 1];
    }
    const bool fullTile = (colBase + TN) <= CDIM;
    #pragma unroll
    for (int mi = 0; mi < 2; ++mi) {
        #pragma unroll
        for (int half = 0; half < 2; ++half) {
            const int rl  = wm * 32 + mi * 16 + groupID + half * 8;
            const float fxr = qxS[rl];
            float fq[8];
            #pragma unroll
            for (int c = 0; c < 8; ++c) fq[c] = fxr * qwr[c];
            float s0 = 0.f, s1 = 0.f;
            if (fullTile) {
                #pragma unroll
                for (int ni = 0; ni < 4; ++ni) {
                    float fa0 = (float)acc[mi][ni][half * 2 + 0];
                    float fa1 = (float)acc[mi][ni][half * 2 + 1];
                    s0 += ex2(fa0 * fq[2 * ni]);
                    s1 += ex2(fa1 * fq[2 * ni + 1]);
                }
            } else {
                #pragma unroll
                for (int ni = 0; ni < 4; ++ni) {
                    #pragma unroll
                    for (int cc = 0; cc < 2; ++cc) {
                        const int col = colBase + wn * 32 + ni * 8 + tid4 * 2 + cc;
                        if (col < CDIM) {
                            float fa = (float)acc[mi][ni][half * 2 + cc];
                            s0 += ex2(fa * fq[2 * ni + cc]);
                        }
                    }
                }
            }
            float s = s0 + s1;
            s += __shfl_xor_sync(0xffffffffu, s, 1);
            s += __shfl_xor_sync(0xffffffffu, s, 2);
            if (tid4 == 0) red[rl * 4 + wn] = s;
        }
    }
    __syncthreads();
    if (t < TM) {
        float s = red[t * 4 + 0] + red[t * 4 + 1] + red[t * 4 + 2] + red[t * 4 + 3];
        g_partial[(rowBase + t) * NT2 + blockIdx.y] = s;
    }
}

// ------ exact fp32 target logit + margin fixup term ---------------------------
// Fixup replicates tile rounding order EXACTLY so the unmargined label term
// cancels bit-for-bit: fxr = fx*(S*L2E); fq = fxr*fw; tt = (float)id * fq.
__global__ void target_kernel(const float* __restrict__ input,
                              const void*  __restrict__ label,
                              const float* __restrict__ weight) {
    int w    = (blockIdx.x * blockDim.x + threadIdx.x) >> 5;
    int lane = threadIdx.x & 31;
    if (w >= BDIM) return;
    int lab = get_label(label, w);
    const float4* xr = (const float4*)(input  + (long long)w   * DDIM);
    const float4* wr = (const float4*)(weight + (long long)lab * DDIM);
    float s = 0.f;
    #pragma unroll 4
    for (int k = lane; k < DDIM / 4; k += 32) {
        float4 a = xr[k], b = wr[k];
        s += a.x * b.x + a.y * b.y + a.z * b.z + a.w * b.w;
    }
    const int* xqi = (const int*)(g_xq + ((long long)w   << 9));
    const int* wqi = (const int*)(g_wq + ((long long)lab << 9));
    int id = 0;
    #pragma unroll 4
    for (int k = lane; k < DDIM / 4; k += 32)
        id = __dp4a(xqi[k], wqi[k], id);
    #pragma unroll
    for (int off = 16; off >= 1; off >>= 1) {
        s  += __shfl_xor_sync(0xffffffffu, s, off);
        id += __shfl_xor_sync(0xffffffffu, id, off);
    }
    if (lane == 0) {
        g_tgt[w] = SCALE * (s * g_rnx[w] * g_rwn[lab] - MARGIN);
        float fxr = g_fx[w] * (SCALE * L2E);
        float fq  = fxr * g_fw[lab];
        float tt  = (float)id * fq;
        g_fix[w]  = ex2(tt - (SCALE * MARGIN * L2E)) - ex2(tt);
    }
}

// ---------------- per-row logsumexp + margin fixup + loss ---------------------
__global__ void fin1_kernel() {
    int r = blockIdx.x;
    float s = 0.f;
    for (int i = threadIdx.x; i < NT2; i += blockDim.x)
        s += g_partial[r * NT2 + i];
    #pragma unroll
    for (int off = 16; off >= 1; off >>= 1)
        s += __shfl_xor_sync(0xffffffffu, s, off);
    __shared__ float sm[4];
    int lane = threadIdx.x & 31, wid = threadIdx.x >> 5;
    if (lane == 0) sm[wid] = s;
    __syncthreads();
    if (threadIdx.x == 0) {
        float tot = sm[0] + sm[1] + sm[2] + sm[3] + g_fix[r];
        g_rowloss[r] = logf(tot) - g_tgt[r];
    }
}
__global__ void fin2_kernel(float* __restrict__ out) {
    __shared__ float sm[32];
    float s = g_rowloss[threadIdx.x];
    #pragma unroll
    for (int off = 16; off >= 1; off >>= 1)
        s += __shfl_xor_sync(0xffffffffu, s, off);
    int lane = threadIdx.x & 31, wid = threadIdx.x >> 5;
    if (lane == 0) sm[wid] = s;
    __syncthreads();
    if (wid == 0) {
        float v = sm[lane];
        #pragma unroll
        for (int off = 16; off >= 1; off >>= 1)
            v += __shfl_xor_sync(0xffffffffu, v, off);
        if (lane == 0) out[0] = v * (1.0f / (float)BDIM);
    }
}

// ---------------- launch ------------------------------------------------------
extern "C" void kernel_launch(void* const* d_in, const int* in_sizes, int n_in,
                              void* d_out, int out_size) {
    const float* input  = (const float*)d_in[0];
    const void*  label  = d_in[1];
    const float* weight = (const float*)d_in[2];
    float* out = (float*)d_out;

    cudaFuncSetAttribute(tile_kernel, cudaFuncAttributeMaxDynamicSharedMemorySize, SMEM_TOTAL);

    detect_kernel<<<1, 256>>>(label);
    norm_quant_kernel<<<(BDIM * 32 + 255) / 256, 256>>>(input, BDIM, 0);
    norm_quant_kernel<<<(CDIM * 32 + 255) / 256, 256>>>(weight, CDIM, 1);

    dim3 grid(NBT, NT2);   // batch fast-varying -> weight tiles shared via L2
    tile_kernel<<<grid, 256, SMEM_TOTAL>>>();

    target_kernel<<<(BDIM * 32 + 255) / 256, 256>>>(input, label, weight);
    fin1_kernel<<<BDIM, 128>>>();
    fin2_kernel<<<1, BDIM>>>(out);
}